// round 5
// baseline (speedup 1.0000x reference)
#include <cuda_runtime.h>
#include <math.h>

#define B    64
#define D    128
#define LC   1024
#define LQ   256
#define NEG_INF -1e30f
#define TS   128      // CTA tile (M and N)
#define KC   8        // K chunk
#define PADW 132      // padded smem row (floats)
#define NT   512      // threads per CTA

typedef unsigned long long ull;

// packed fp32x2 FMA: acc.lo += a.lo*b.lo ; acc.hi += a.hi*b.hi
__device__ __forceinline__ void ffma2(ull& acc, ull a, ull b) {
    asm("fma.rn.f32x2 %0, %1, %2, %0;" : "+l"(acc) : "l"(a), "l"(b));
}
__device__ __forceinline__ ull dup2(float a) {
    ull r; asm("mov.b64 %0, {%1, %1};" : "=l"(r) : "f"(a)); return r;
}
__device__ __forceinline__ float lo32(ull v) { return __uint_as_float((unsigned)v); }
__device__ __forceinline__ float hi32(ull v) { return __uint_as_float((unsigned)(v >> 32)); }

// ---------------- scratch (device globals: no allocation allowed) ----------------
__device__ float g_E[(size_t)B * LC * LQ];   // exp(S), 64 MiB
__device__ float g_M[(size_t)B * LQ * D];    // S2^T @ Ct
__device__ float g_rowsum[B * LC];
__device__ float g_colsum[B * LQ];
__device__ float g_cw1[B * LC];
__device__ float g_qw2[B * LQ];
__device__ float g_fc[B * LC];               // exp((1-cmask)*NEG_INF)  (0 or 1)
__device__ float g_fq[B * LQ];               // exp((1-qmask)*NEG_INF)

// ---------------- K0: biases, mask factors, zero accumulators ----------------
__global__ void k0_setup(const float* __restrict__ C, const float* __restrict__ Q,
                         const float* __restrict__ cmask, const float* __restrict__ qmask,
                         const float* __restrict__ w) {
    int idx = blockIdx.x * 256 + threadIdx.x;
    if (idx < B * LC) {
        int b = idx >> 10;
        int i = idx & (LC - 1);
        const float* cp = C + (size_t)b * D * LC + i;
        float s = 0.f;
#pragma unroll 4
        for (int dd = 0; dd < D; ++dd) s = fmaf(cp[(size_t)dd * LC], w[dd], s);
        g_cw1[idx] = s;
        g_fc[idx] = expf((1.0f - cmask[idx]) * NEG_INF);
        g_rowsum[idx] = 0.f;
    } else {
        int t = idx - B * LC;
        if (t < B * LQ) {
            int b = t >> 8;
            int j = t & (LQ - 1);
            const float* qp = Q + (size_t)b * D * LQ + j;
            float s = 0.f;
#pragma unroll 4
            for (int dd = 0; dd < D; ++dd) s = fmaf(qp[(size_t)dd * LQ], w[D + dd], s);
            g_qw2[t] = s;
            g_fq[t] = expf((1.0f - qmask[t]) * NEG_INF);
            g_colsum[t] = 0.f;
        }
    }
}

// ---------------- K1: E = exp(S) + row/col exp-sums -------------------------
// grid (LQ/128, LC/128, B), 512 thr, 128x128 tile, 8x4 micro (FFMA2 j-pairs)
__global__ __launch_bounds__(NT) void k1_score(const float* __restrict__ C,
                                               const float* __restrict__ Q,
                                               const float* __restrict__ w) {
    int b = blockIdx.z;
    int i0 = blockIdx.y * TS;
    int j0 = blockIdx.x * TS;

    __shared__ __align__(16) float As[KC][PADW];   // [k=d][i]  C*w3
    __shared__ __align__(16) float Bs[KC][PADW];   // [k=d][j]  Q
    __shared__ float srow[TS], scol[TS];

    int tid = threadIdx.x;
    int tm = tid & 15;      // i group (8 rows each)
    int tn = tid >> 4;      // j group (4 cols each), 0..31
    if (tid < TS) srow[tid] = 0.f;
    else if (tid < 2 * TS) scol[tid - TS] = 0.f;

    ull acc[8][2];
#pragma unroll
    for (int r = 0; r < 8; ++r) { acc[r][0] = 0ull; acc[r][1] = 0ull; }

    const float* Cb = C + (size_t)b * D * LC;
    const float* Qb = Q + (size_t)b * D * LQ;

    bool loadA = tid < 256;
    int lt = loadA ? tid : tid - 256;
    int lr = lt >> 5;          // 0..7 (k within chunk)
    int lc = (lt & 31) * 4;    // 0..124

    float4 v;
    {   // prefetch chunk 0
        if (loadA) {
            float w3v = w[2 * D + lr];
            v = *(const float4*)(Cb + (size_t)lr * LC + i0 + lc);
            v.x *= w3v; v.y *= w3v; v.z *= w3v; v.w *= w3v;
        } else {
            v = *(const float4*)(Qb + (size_t)lr * LQ + j0 + lc);
        }
    }

    for (int k0 = 0; k0 < D; k0 += KC) {
        __syncthreads();
        if (loadA) *(float4*)&As[lr][lc] = v;
        else       *(float4*)&Bs[lr][lc] = v;
        __syncthreads();
        if (k0 + KC < D) {
            if (loadA) {
                float w3v = w[2 * D + k0 + KC + lr];
                v = *(const float4*)(Cb + (size_t)(k0 + KC + lr) * LC + i0 + lc);
                v.x *= w3v; v.y *= w3v; v.z *= w3v; v.w *= w3v;
            } else {
                v = *(const float4*)(Qb + (size_t)(k0 + KC + lr) * LQ + j0 + lc);
            }
        }
#pragma unroll
        for (int kk = 0; kk < KC; ++kk) {
            float4 a03 = *(const float4*)&As[kk][tm * 4];
            float4 a47 = *(const float4*)&As[kk][64 + tm * 4];
            ulonglong2 bp = *(const ulonglong2*)&Bs[kk][tn * 4];
            ull ad[8];
            ad[0] = dup2(a03.x); ad[1] = dup2(a03.y); ad[2] = dup2(a03.z); ad[3] = dup2(a03.w);
            ad[4] = dup2(a47.x); ad[5] = dup2(a47.y); ad[6] = dup2(a47.z); ad[7] = dup2(a47.w);
#pragma unroll
            for (int r = 0; r < 8; ++r) {
                ffma2(acc[r][0], ad[r], bp.x);
                ffma2(acc[r][1], ad[r], bp.y);
            }
        }
    }

    // ---- epilogue: biases, exp, store E, reduce row/col sums ----
    int il[8];
#pragma unroll
    for (int t = 0; t < 4; ++t) { il[t] = tm * 4 + t; il[4 + t] = 64 + tm * 4 + t; }
    int jb = j0 + tn * 4;
    float cw[8], fcv[8], qw[4], fqv[4];
#pragma unroll
    for (int r = 0; r < 8; ++r) { cw[r] = g_cw1[b * LC + i0 + il[r]]; fcv[r] = g_fc[b * LC + i0 + il[r]]; }
#pragma unroll
    for (int c = 0; c < 4; ++c) { qw[c] = g_qw2[b * LQ + jb + c]; fqv[c] = g_fq[b * LQ + jb + c]; }

    float rowp[8] = {0.f,0.f,0.f,0.f,0.f,0.f,0.f,0.f};
    float colp[4] = {0.f,0.f,0.f,0.f};
#pragma unroll
    for (int r = 0; r < 8; ++r) {
        float ev[4];
#pragma unroll
        for (int c = 0; c < 4; ++c) {
            float s = (c & 1) ? hi32(acc[r][c >> 1]) : lo32(acc[r][c >> 1]);
            float e = expf(s + cw[r] + qw[c]);
            ev[c] = e;
            rowp[r] = fmaf(e, fqv[c], rowp[r]);
            colp[c] = fmaf(e, fcv[r], colp[c]);
        }
        *(float4*)(g_E + ((size_t)b * LC + i0 + il[r]) * LQ + jb) =
            make_float4(ev[0], ev[1], ev[2], ev[3]);
    }
    __syncthreads();   // srow/scol init visible
#pragma unroll
    for (int r = 0; r < 8; ++r) atomicAdd(&srow[il[r]], rowp[r]);
#pragma unroll
    for (int c = 0; c < 4; ++c) atomicAdd(&scol[tn * 4 + c], colp[c]);
    __syncthreads();
    if (tid < TS) atomicAdd(&g_rowsum[b * LC + i0 + tid], srow[tid]);
    else if (tid < 2 * TS) atomicAdd(&g_colsum[b * LQ + j0 + tid - TS], scol[tid - TS]);
}

// ---------------- K4: M[b,j,dd] = (sum_i E[i,j]*fc[i]*C[dd,i]) / colsum[j] ---
// grid (LQ/128, B), 512 thr, K = LC = 1024
__global__ __launch_bounds__(NT) void k4_m(const float* __restrict__ C) {
    int b = blockIdx.y;
    int j0 = blockIdx.x * TS;

    __shared__ __align__(16) float As[KC][PADW];   // [k=i][j]   E*fc
    __shared__ __align__(16) float Bs[KC][PADW];   // [k=i][dd]  C^T

    int tid = threadIdx.x;
    int tm = tid & 15;   // j group (8)
    int tn = tid >> 4;   // dd group (4), 0..31

    ull acc[8][2];
#pragma unroll
    for (int r = 0; r < 8; ++r) { acc[r][0] = 0ull; acc[r][1] = 0ull; }

    const float* Cb = C + (size_t)b * D * LC;
    const float* Eb = g_E + (size_t)b * LC * LQ;

    bool loadA = tid < 256;
    int lt = loadA ? tid : tid - 256;
    int lr = lt >> 5, lc = (lt & 31) * 4;   // direct (E)
    int bd = lt >> 1, bk = (lt & 1) * 4;    // transpose (C)

    float4 v;
    {
        if (loadA) {
            float f = g_fc[b * LC + lr];
            v = *(const float4*)(Eb + (size_t)lr * LQ + j0 + lc);
            v.x *= f; v.y *= f; v.z *= f; v.w *= f;
        } else {
            v = *(const float4*)(Cb + (size_t)bd * LC + bk);
        }
    }

    for (int k0 = 0; k0 < LC; k0 += KC) {
        __syncthreads();
        if (loadA) {
            *(float4*)&As[lr][lc] = v;
        } else {
            Bs[bk + 0][bd] = v.x;
            Bs[bk + 1][bd] = v.y;
            Bs[bk + 2][bd] = v.z;
            Bs[bk + 3][bd] = v.w;
        }
        __syncthreads();
        if (k0 + KC < LC) {
            if (loadA) {
                float f = g_fc[b * LC + k0 + KC + lr];
                v = *(const float4*)(Eb + (size_t)(k0 + KC + lr) * LQ + j0 + lc);
                v.x *= f; v.y *= f; v.z *= f; v.w *= f;
            } else {
                v = *(const float4*)(Cb + (size_t)bd * LC + k0 + KC + bk);
            }
        }
#pragma unroll
        for (int kk = 0; kk < KC; ++kk) {
            float4 a03 = *(const float4*)&As[kk][tm * 4];
            float4 a47 = *(const float4*)&As[kk][64 + tm * 4];
            ulonglong2 bp = *(const ulonglong2*)&Bs[kk][tn * 4];
            ull ad[8];
            ad[0] = dup2(a03.x); ad[1] = dup2(a03.y); ad[2] = dup2(a03.z); ad[3] = dup2(a03.w);
            ad[4] = dup2(a47.x); ad[5] = dup2(a47.y); ad[6] = dup2(a47.z); ad[7] = dup2(a47.w);
#pragma unroll
            for (int r = 0; r < 8; ++r) {
                ffma2(acc[r][0], ad[r], bp.x);
                ffma2(acc[r][1], ad[r], bp.y);
            }
        }
    }

    int jl[8];
#pragma unroll
    for (int t = 0; t < 4; ++t) { jl[t] = tm * 4 + t; jl[4 + t] = 64 + tm * 4 + t; }
    float cinv[8];
#pragma unroll
    for (int r = 0; r < 8; ++r) cinv[r] = 1.0f / g_colsum[b * LQ + j0 + jl[r]];
#pragma unroll
    for (int r = 0; r < 8; ++r) {
        *(float4*)(g_M + ((size_t)b * LQ + j0 + jl[r]) * D + tn * 4) =
            make_float4(lo32(acc[r][0]) * cinv[r], hi32(acc[r][0]) * cinv[r],
                        lo32(acc[r][1]) * cinv[r], hi32(acc[r][1]) * cinv[r]);
    }
}

// ---------------- K5: A & Bmat fused + all 4 output channels -----------------
// grid (LC/128, B), 512 thr, K = LQ = 256
__global__ __launch_bounds__(NT) void k5_out(const float* __restrict__ C,
                                             const float* __restrict__ Q,
                                             float* __restrict__ out) {
    int b = blockIdx.y;
    int i0 = blockIdx.x * TS;

    __shared__ __align__(16) float As[KC][PADW];   // [k=j][i]   E*fq
    __shared__ __align__(16) float Bq[KC][PADW];   // [k=j][dd]  Q^T
    __shared__ __align__(16) float Bm[KC][PADW];   // [k=j][dd]  M
    __shared__ float fqs[LQ];

    int tid = threadIdx.x;
    int tm = tid & 15;   // i group (8)
    int tn = tid >> 4;   // dd group (4), 0..31
    if (tid < LQ) fqs[tid] = g_fq[b * LQ + tid];

    ull accA[8][2], accB[8][2];
#pragma unroll
    for (int r = 0; r < 8; ++r) {
        accA[r][0] = 0ull; accA[r][1] = 0ull;
        accB[r][0] = 0ull; accB[r][1] = 0ull;
    }

    const float* Cb = C + (size_t)b * D * LC;
    const float* Qb = Q + (size_t)b * D * LQ;
    const float* Eb = g_E + (size_t)b * LC * LQ;
    const float* Mb = g_M + (size_t)b * LQ * D;

    bool loadE = tid < 256;
    int lt = loadE ? tid : tid - 256;
    int ar = lt >> 1, ak = (lt & 1) * 4;    // transpose (E over i, or Q over dd)
    int mr = tid >> 6, mc = (tid & 63) * 2; // direct (M), float2 by all threads

    float4 v; float2 m2;
    {
        if (loadE) v = *(const float4*)(Eb + (size_t)(i0 + ar) * LQ + ak);
        else       v = *(const float4*)(Qb + (size_t)ar * LQ + ak);
        m2 = *(const float2*)(Mb + (size_t)mr * D + mc);
    }

    for (int k0 = 0; k0 < LQ; k0 += KC) {
        __syncthreads();
        if (loadE) {
            As[ak + 0][ar] = v.x * fqs[k0 + ak + 0];
            As[ak + 1][ar] = v.y * fqs[k0 + ak + 1];
            As[ak + 2][ar] = v.z * fqs[k0 + ak + 2];
            As[ak + 3][ar] = v.w * fqs[k0 + ak + 3];
        } else {
            Bq[ak + 0][ar] = v.x;
            Bq[ak + 1][ar] = v.y;
            Bq[ak + 2][ar] = v.z;
            Bq[ak + 3][ar] = v.w;
        }
        *(float2*)&Bm[mr][mc] = m2;
        __syncthreads();
        if (k0 + KC < LQ) {
            if (loadE) v = *(const float4*)(Eb + (size_t)(i0 + ar) * LQ + k0 + KC + ak);
            else       v = *(const float4*)(Qb + (size_t)ar * LQ + k0 + KC + ak);
            m2 = *(const float2*)(Mb + (size_t)(k0 + KC + mr) * D + mc);
        }
#pragma unroll
        for (int kk = 0; kk < KC; ++kk) {
            float4 a03 = *(const float4*)&As[kk][tm * 4];
            float4 a47 = *(const float4*)&As[kk][64 + tm * 4];
            ulonglong2 qp = *(const ulonglong2*)&Bq[kk][tn * 4];
            ulonglong2 mp = *(const ulonglong2*)&Bm[kk][tn * 4];
            ull ad[8];
            ad[0] = dup2(a03.x); ad[1] = dup2(a03.y); ad[2] = dup2(a03.z); ad[3] = dup2(a03.w);
            ad[4] = dup2(a47.x); ad[5] = dup2(a47.y); ad[6] = dup2(a47.z); ad[7] = dup2(a47.w);
#pragma unroll
            for (int r = 0; r < 8; ++r) {
                ffma2(accA[r][0], ad[r], qp.x);
                ffma2(accA[r][1], ad[r], qp.y);
                ffma2(accB[r][0], ad[r], mp.x);
                ffma2(accB[r][1], ad[r], mp.y);
            }
        }
    }

    int il[8];
#pragma unroll
    for (int t = 0; t < 4; ++t) { il[t] = tm * 4 + t; il[4 + t] = 64 + tm * 4 + t; }
    float rinv[8];
#pragma unroll
    for (int r = 0; r < 8; ++r) rinv[r] = 1.0f / g_rowsum[b * LC + i0 + il[r]];

    size_t ob = (size_t)b * 4 * D * LC;
#pragma unroll
    for (int c = 0; c < 4; ++c) {
        int dd = tn * 4 + c;
        int c2 = c >> 1;
#pragma unroll
        for (int rq = 0; rq < 2; ++rq) {
            int ib = i0 + rq * 64 + tm * 4;
            int r0 = rq * 4;
            float4 c4 = *(const float4*)(Cb + (size_t)dd * LC + ib);
            float aA[4], aB[4];
#pragma unroll
            for (int t = 0; t < 4; ++t) {
                aA[t] = ((c & 1) ? hi32(accA[r0 + t][c2]) : lo32(accA[r0 + t][c2])) * rinv[r0 + t];
                aB[t] = ((c & 1) ? hi32(accB[r0 + t][c2]) : lo32(accB[r0 + t][c2])) * rinv[r0 + t];
            }
            float4 a4 = make_float4(aA[0], aA[1], aA[2], aA[3]);
            float4 b4 = make_float4(aB[0], aB[1], aB[2], aB[3]);
            *(float4*)(out + ob + (size_t)dd * LC + ib) = c4;                              // Ct
            *(float4*)(out + ob + (size_t)(D + dd) * LC + ib) = a4;                        // A
            *(float4*)(out + ob + (size_t)(2 * D + dd) * LC + ib) =
                make_float4(c4.x * a4.x, c4.y * a4.y, c4.z * a4.z, c4.w * a4.w);           // Ct*A
            *(float4*)(out + ob + (size_t)(3 * D + dd) * LC + ib) =
                make_float4(c4.x * b4.x, c4.y * b4.y, c4.z * b4.z, c4.w * b4.w);           // Ct*Bmat
        }
    }
}

// ---------------- launch ------------------------------------------------------
extern "C" void kernel_launch(void* const* d_in, const int* in_sizes, int n_in,
                              void* d_out, int out_size) {
    const float* C = (const float*)d_in[0];
    const float* Q = (const float*)d_in[1];
    const float* cmask = (const float*)d_in[2];
    const float* qmask = (const float*)d_in[3];
    const float* w = (const float*)d_in[4];
    float* out = (float*)d_out;

    k0_setup<<<(B * LC + B * LQ) / 256, 256>>>(C, Q, cmask, qmask, w);

    dim3 g1(LQ / TS, LC / TS, B);
    k1_score<<<g1, NT>>>(C, Q, w);

    dim3 g4(LQ / TS, B);
    k4_m<<<g4, NT>>>(C);

    dim3 g5(LC / TS, B);
    k5_out<<<g5, NT>>>(C, Q, out);
}

// round 6
// speedup vs baseline: 1.2231x; 1.2231x over previous
#include <cuda_runtime.h>
#include <math.h>

#define B    64
#define D    128
#define LC   1024
#define LQ   256
#define NEG_INF -1e30f
#define SA   132     // smem row stride for 128-wide tiles (132%32==4 -> conflict-free frags)
#define SB   68      // smem row stride for 64-wide tiles  (68%32==4)

// ---------------- scratch (device globals: no allocation allowed) ----------------
__device__ float g_E[(size_t)B * LC * LQ];   // exp(S), 64 MiB
__device__ float g_M[(size_t)B * LQ * D];    // S2^T @ Ct (already / colsum)
__device__ float g_rowsum[B * LC];
__device__ float g_colsum[B * LQ];
__device__ float g_cw1[B * LC];
__device__ float g_qw2[B * LQ];
__device__ float g_fc[B * LC];               // exp((1-cmask)*NEG_INF)  (0 or 1)
__device__ float g_fq[B * LQ];               // exp((1-qmask)*NEG_INF)

// ---------------- tf32 helpers ----------------
__device__ __forceinline__ unsigned f2t(float x) {
    unsigned u; asm("cvt.rna.tf32.f32 %0, %1;" : "=r"(u) : "f"(x)); return u;
}
__device__ __forceinline__ void tsplit(float x, unsigned& h, unsigned& l) {
    h = f2t(x);
    l = f2t(x - __uint_as_float(h));
}
// D += A(16x8) * B(8x8), tf32 inputs, f32 accum
__device__ __forceinline__ void mma8(float* c, const unsigned* a, const unsigned* b) {
    asm volatile(
        "mma.sync.aligned.m16n8k8.row.col.f32.tf32.tf32.f32 "
        "{%0,%1,%2,%3},{%4,%5,%6,%7},{%8,%9},{%0,%1,%2,%3};"
        : "+f"(c[0]), "+f"(c[1]), "+f"(c[2]), "+f"(c[3])
        : "r"(a[0]), "r"(a[1]), "r"(a[2]), "r"(a[3]), "r"(b[0]), "r"(b[1]));
}

// ---------------- K0: biases, mask factors, zero accumulators ----------------
__global__ void k0_setup(const float* __restrict__ C, const float* __restrict__ Q,
                         const float* __restrict__ cmask, const float* __restrict__ qmask,
                         const float* __restrict__ w) {
    int idx = blockIdx.x * 256 + threadIdx.x;
    if (idx < B * LC) {
        int b = idx >> 10;
        int i = idx & (LC - 1);
        const float* cp = C + (size_t)b * D * LC + i;
        float s = 0.f;
#pragma unroll 4
        for (int dd = 0; dd < D; ++dd) s = fmaf(cp[(size_t)dd * LC], w[dd], s);
        g_cw1[idx] = s;
        g_fc[idx] = expf((1.0f - cmask[idx]) * NEG_INF);
        g_rowsum[idx] = 0.f;
    } else {
        int t = idx - B * LC;
        if (t < B * LQ) {
            int b = t >> 8;
            int j = t & (LQ - 1);
            const float* qp = Q + (size_t)b * D * LQ + j;
            float s = 0.f;
#pragma unroll 4
            for (int dd = 0; dd < D; ++dd) s = fmaf(qp[(size_t)dd * LQ], w[D + dd], s);
            g_qw2[t] = s;
            g_fq[t] = expf((1.0f - qmask[t]) * NEG_INF);
            g_colsum[t] = 0.f;
        }
    }
}

// ---------------- K1: E = exp(S) + row/col exp-sums (tf32x3 MMA) -------------
// grid (LQ/128, LC/128, B), 256 thr.  M=i(128) N=j(128) K=d(128)
__global__ __launch_bounds__(256) void k1_score(const float* __restrict__ C,
                                                const float* __restrict__ Q,
                                                const float* __restrict__ w) {
    int b = blockIdx.z, i0 = blockIdx.y * 128, j0 = blockIdx.x * 128;

    __shared__ float As[32][SA];   // [k=d][m=i]  C*w3
    __shared__ float Bs[32][SA];   // [k=d][n=j]  Q
    __shared__ float scw[128], sfcs[128], sqw[128], sfqs[128], srow[128], scol[128];

    int tid = threadIdx.x;
    int wid = tid >> 5, lane = tid & 31, g = lane >> 2, t = lane & 3;
    int wm = wid & 3, wn = wid >> 2;     // warp tile: 32(m) x 64(n)

    float acc[2][8][4];
#pragma unroll
    for (int mt = 0; mt < 2; ++mt)
#pragma unroll
        for (int nt = 0; nt < 8; ++nt)
#pragma unroll
            for (int c = 0; c < 4; ++c) acc[mt][nt][c] = 0.f;

    const float* Cb = C + (size_t)b * D * LC;
    const float* Qb = Q + (size_t)b * D * LQ;

    int qm = tid & 31, kr = tid >> 5;    // loader: m-quad, k-row

    float4 pa[4], pb[4];
#pragma unroll
    for (int p = 0; p < 4; ++p) {        // prefetch chunk 0
        int k = kr + 8 * p;
        float w3 = w[2 * D + k];
        float4 v = *(const float4*)(Cb + (size_t)k * LC + i0 + 4 * qm);
        v.x *= w3; v.y *= w3; v.z *= w3; v.w *= w3;
        pa[p] = v;
        pb[p] = *(const float4*)(Qb + (size_t)k * LQ + j0 + 4 * qm);
    }

    for (int kc = 0; kc < D; kc += 32) {
        __syncthreads();
#pragma unroll
        for (int p = 0; p < 4; ++p) {
            *(float4*)&As[kr + 8 * p][4 * qm] = pa[p];
            *(float4*)&Bs[kr + 8 * p][4 * qm] = pb[p];
        }
        __syncthreads();
        if (kc + 32 < D) {
#pragma unroll
            for (int p = 0; p < 4; ++p) {
                int k = kc + 32 + kr + 8 * p;
                float w3 = w[2 * D + k];
                float4 v = *(const float4*)(Cb + (size_t)k * LC + i0 + 4 * qm);
                v.x *= w3; v.y *= w3; v.z *= w3; v.w *= w3;
                pa[p] = v;
                pb[p] = *(const float4*)(Qb + (size_t)k * LQ + j0 + 4 * qm);
            }
        }
#pragma unroll
        for (int k8 = 0; k8 < 4; ++k8) {
            int kk = 8 * k8;
            unsigned ah[2][4], al[2][4];
#pragma unroll
            for (int mt = 0; mt < 2; ++mt) {
                int R = wm * 32 + mt * 16 + g;
                tsplit(As[kk + t][R],       ah[mt][0], al[mt][0]);
                tsplit(As[kk + t][R + 8],   ah[mt][1], al[mt][1]);
                tsplit(As[kk + t + 4][R],     ah[mt][2], al[mt][2]);
                tsplit(As[kk + t + 4][R + 8], ah[mt][3], al[mt][3]);
            }
#pragma unroll
            for (int nt = 0; nt < 8; ++nt) {
                int NN = wn * 64 + nt * 8 + g;
                unsigned bh[2], bl[2];
                tsplit(Bs[kk + t][NN],     bh[0], bl[0]);
                tsplit(Bs[kk + t + 4][NN], bh[1], bl[1]);
#pragma unroll
                for (int mt = 0; mt < 2; ++mt) {
                    mma8(acc[mt][nt], ah[mt], bh);
                    mma8(acc[mt][nt], al[mt], bh);
                    mma8(acc[mt][nt], ah[mt], bl);
                }
            }
        }
    }

    // ---- epilogue ----
    __syncthreads();
    if (tid < 128) {
        scw[tid]  = g_cw1[b * LC + i0 + tid];
        sfcs[tid] = g_fc[b * LC + i0 + tid];
        srow[tid] = 0.f;
    } else {
        int j = tid - 128;
        sqw[j]  = g_qw2[b * LQ + j0 + j];
        sfqs[j] = g_fq[b * LQ + j0 + j];
        scol[j] = 0.f;
    }
    __syncthreads();

    float rowp[4] = {0.f, 0.f, 0.f, 0.f};
    float colp[16];
#pragma unroll
    for (int c = 0; c < 16; ++c) colp[c] = 0.f;

#pragma unroll
    for (int mt = 0; mt < 2; ++mt)
#pragma unroll
        for (int half = 0; half < 2; ++half) {
            int rl = wm * 32 + mt * 16 + g + 8 * half;
            float cwv = scw[rl], fcv = sfcs[rl];
#pragma unroll
            for (int nt = 0; nt < 8; ++nt) {
                int cl = wn * 64 + nt * 8 + 2 * t;
                float e0 = expf(acc[mt][nt][half * 2 + 0] + cwv + sqw[cl]);
                float e1 = expf(acc[mt][nt][half * 2 + 1] + cwv + sqw[cl + 1]);
                *(float2*)(g_E + ((size_t)b * LC + i0 + rl) * LQ + j0 + cl) =
                    make_float2(e0, e1);
                rowp[mt * 2 + half] += e0 * sfqs[cl] + e1 * sfqs[cl + 1];
                colp[nt * 2 + 0] += e0 * fcv;
                colp[nt * 2 + 1] += e1 * fcv;
            }
        }

#pragma unroll
    for (int r = 0; r < 4; ++r) {
        rowp[r] += __shfl_xor_sync(0xffffffffu, rowp[r], 1);
        rowp[r] += __shfl_xor_sync(0xffffffffu, rowp[r], 2);
    }
    if (t == 0) {
#pragma unroll
        for (int mt = 0; mt < 2; ++mt)
#pragma unroll
            for (int half = 0; half < 2; ++half)
                atomicAdd(&srow[wm * 32 + mt * 16 + g + 8 * half], rowp[mt * 2 + half]);
    }
#pragma unroll
    for (int c = 0; c < 16; ++c) {
        colp[c] += __shfl_xor_sync(0xffffffffu, colp[c], 4);
        colp[c] += __shfl_xor_sync(0xffffffffu, colp[c], 8);
        colp[c] += __shfl_xor_sync(0xffffffffu, colp[c], 16);
    }
    if (g == 0) {
#pragma unroll
        for (int nt = 0; nt < 8; ++nt)
#pragma unroll
            for (int par = 0; par < 2; ++par)
                atomicAdd(&scol[wn * 64 + nt * 8 + 2 * t + par], colp[nt * 2 + par]);
    }
    __syncthreads();
    if (tid < 128) atomicAdd(&g_rowsum[b * LC + i0 + tid], srow[tid]);
    else           atomicAdd(&g_colsum[b * LQ + j0 + tid - 128], scol[tid - 128]);
}

// ---------------- K4: M[j][dd] = (sum_i E[i][j]*fc[i]*C[dd][i]) / colsum[j] --
// grid (LQ/128, B), 256 thr.  M=j(128) N=dd(128) K=i(1024)
__global__ __launch_bounds__(256) void k4_m(const float* __restrict__ C) {
    int b = blockIdx.y, j0 = blockIdx.x * 128;

    __shared__ float As[32][SA];   // [k=i][m=j]   E*fc
    __shared__ float Bs[32][SA];   // [k=i][n=dd]  C^T

    int tid = threadIdx.x;
    int wid = tid >> 5, lane = tid & 31, g = lane >> 2, t = lane & 3;
    int wm = wid & 3, wn = wid >> 2;

    float acc[2][8][4];
#pragma unroll
    for (int mt = 0; mt < 2; ++mt)
#pragma unroll
        for (int nt = 0; nt < 8; ++nt)
#pragma unroll
            for (int c = 0; c < 4; ++c) acc[mt][nt][c] = 0.f;

    const float* Cb = C + (size_t)b * D * LC;
    const float* Eb = g_E + (size_t)b * LC * LQ;

    int qm = tid & 31, kr = tid >> 5;     // A loader
    int dd = tid & 127, kq = tid >> 7;    // B loader (transpose)

    float4 va[4], vb[4];
#pragma unroll
    for (int p = 0; p < 4; ++p) {
        int i = kr + 8 * p;
        float f = g_fc[b * LC + i];
        float4 v = *(const float4*)(Eb + (size_t)i * LQ + j0 + 4 * qm);
        v.x *= f; v.y *= f; v.z *= f; v.w *= f;
        va[p] = v;
        vb[p] = *(const float4*)(Cb + (size_t)dd * LC + 4 * (kq + 2 * p));
    }

    for (int kc = 0; kc < LC; kc += 32) {
        __syncthreads();
#pragma unroll
        for (int p = 0; p < 4; ++p) {
            *(float4*)&As[kr + 8 * p][4 * qm] = va[p];
            int kb = 4 * (kq + 2 * p);
            Bs[kb + 0][dd] = vb[p].x;
            Bs[kb + 1][dd] = vb[p].y;
            Bs[kb + 2][dd] = vb[p].z;
            Bs[kb + 3][dd] = vb[p].w;
        }
        __syncthreads();
        if (kc + 32 < LC) {
#pragma unroll
            for (int p = 0; p < 4; ++p) {
                int i = kc + 32 + kr + 8 * p;
                float f = g_fc[b * LC + i];
                float4 v = *(const float4*)(Eb + (size_t)i * LQ + j0 + 4 * qm);
                v.x *= f; v.y *= f; v.z *= f; v.w *= f;
                va[p] = v;
                vb[p] = *(const float4*)(Cb + (size_t)dd * LC + kc + 32 + 4 * (kq + 2 * p));
            }
        }
#pragma unroll
        for (int k8 = 0; k8 < 4; ++k8) {
            int kk = 8 * k8;
            unsigned ah[2][4], al[2][4];
#pragma unroll
            for (int mt = 0; mt < 2; ++mt) {
                int R = wm * 32 + mt * 16 + g;
                tsplit(As[kk + t][R],       ah[mt][0], al[mt][0]);
                tsplit(As[kk + t][R + 8],   ah[mt][1], al[mt][1]);
                tsplit(As[kk + t + 4][R],     ah[mt][2], al[mt][2]);
                tsplit(As[kk + t + 4][R + 8], ah[mt][3], al[mt][3]);
            }
#pragma unroll
            for (int nt = 0; nt < 8; ++nt) {
                int NN = wn * 64 + nt * 8 + g;
                unsigned bh[2], bl[2];
                tsplit(Bs[kk + t][NN],     bh[0], bl[0]);
                tsplit(Bs[kk + t + 4][NN], bh[1], bl[1]);
#pragma unroll
                for (int mt = 0; mt < 2; ++mt) {
                    mma8(acc[mt][nt], ah[mt], bh);
                    mma8(acc[mt][nt], al[mt], bh);
                    mma8(acc[mt][nt], ah[mt], bl);
                }
            }
        }
    }

    // ---- epilogue: divide by colsum, store M ----
#pragma unroll
    for (int mt = 0; mt < 2; ++mt)
#pragma unroll
        for (int half = 0; half < 2; ++half) {
            int rl = wm * 32 + mt * 16 + g + 8 * half;
            int jj = j0 + rl;
            float ci = 1.0f / g_colsum[b * LQ + jj];
#pragma unroll
            for (int nt = 0; nt < 8; ++nt) {
                int ddc = wn * 64 + nt * 8 + 2 * t;
                *(float2*)(g_M + ((size_t)b * LQ + jj) * D + ddc) =
                    make_float2(acc[mt][nt][half * 2 + 0] * ci,
                                acc[mt][nt][half * 2 + 1] * ci);
            }
        }
}

// ---------------- K5: A & Bmat (dual GEMM) + 4 output channels ----------------
// grid (D/64, LC/128, B), 256 thr.  M=i(128) N=dd(64) K=j(256)
__global__ __launch_bounds__(256) void k5_out(const float* __restrict__ C,
                                              const float* __restrict__ Q,
                                              float* __restrict__ out) {
    int b = blockIdx.z, i0 = blockIdx.y * 128, dd0 = blockIdx.x * 64;

    __shared__ float As[32][SA];   // [k=j][m=i]   E*fq
    __shared__ float Bq[32][SB];   // [k=j][n=dd]  Q^T
    __shared__ float Bm[32][SB];   // [k=j][n=dd]  M
    __shared__ float sfq[LQ];

    int tid = threadIdx.x;
    int wid = tid >> 5, lane = tid & 31, g = lane >> 2, t = lane & 3;
    int wm = wid & 3, wn = wid >> 2;     // warp tile: 32(m) x 32(n)

    sfq[tid] = g_fq[b * LQ + tid];

    float accA[2][4][4], accB[2][4][4];
#pragma unroll
    for (int mt = 0; mt < 2; ++mt)
#pragma unroll
        for (int nt = 0; nt < 4; ++nt)
#pragma unroll
            for (int c = 0; c < 4; ++c) { accA[mt][nt][c] = 0.f; accB[mt][nt][c] = 0.f; }

    const float* Cb = C + (size_t)b * D * LC;
    const float* Qb = Q + (size_t)b * D * LQ;
    const float* Eb = g_E + (size_t)b * LC * LQ;
    const float* Mb = g_M + (size_t)b * LQ * D;

    int ia = tid & 127, kqa = tid >> 7;        // A loader (transpose)
    int dq = tid & 63,  kq2 = (tid >> 6) & 3;  // Bq loader (transpose)
    int qn = tid & 15,  krm = tid >> 4;        // Bm loader (direct)

    float4 ea[4], qa[2], ma[2];
#pragma unroll
    for (int p = 0; p < 4; ++p)
        ea[p] = *(const float4*)(Eb + (size_t)(i0 + ia) * LQ + 4 * (kqa + 2 * p));
#pragma unroll
    for (int p = 0; p < 2; ++p) {
        qa[p] = *(const float4*)(Qb + (size_t)(dd0 + dq) * LQ + 4 * (kq2 + 4 * p));
        ma[p] = *(const float4*)(Mb + (size_t)(krm + 16 * p) * D + dd0 + 4 * qn);
    }

    for (int kc = 0; kc < LQ; kc += 32) {
        __syncthreads();
#pragma unroll
        for (int p = 0; p < 4; ++p) {
            int ka = 4 * (kqa + 2 * p);
            As[ka + 0][ia] = ea[p].x * sfq[kc + ka + 0];
            As[ka + 1][ia] = ea[p].y * sfq[kc + ka + 1];
            As[ka + 2][ia] = ea[p].z * sfq[kc + ka + 2];
            As[ka + 3][ia] = ea[p].w * sfq[kc + ka + 3];
        }
#pragma unroll
        for (int p = 0; p < 2; ++p) {
            int kb = 4 * (kq2 + 4 * p);
            Bq[kb + 0][dq] = qa[p].x;
            Bq[kb + 1][dq] = qa[p].y;
            Bq[kb + 2][dq] = qa[p].z;
            Bq[kb + 3][dq] = qa[p].w;
            *(float4*)&Bm[krm + 16 * p][4 * qn] = ma[p];
        }
        __syncthreads();
        if (kc + 32 < LQ) {
#pragma unroll
            for (int p = 0; p < 4; ++p)
                ea[p] = *(const float4*)(Eb + (size_t)(i0 + ia) * LQ + kc + 32 + 4 * (kqa + 2 * p));
#pragma unroll
            for (int p = 0; p < 2; ++p) {
                qa[p] = *(const float4*)(Qb + (size_t)(dd0 + dq) * LQ + kc + 32 + 4 * (kq2 + 4 * p));
                ma[p] = *(const float4*)(Mb + (size_t)(kc + 32 + krm + 16 * p) * D + dd0 + 4 * qn);
            }
        }
#pragma unroll
        for (int k8 = 0; k8 < 4; ++k8) {
            int kk = 8 * k8;
            unsigned ah[2][4], al[2][4];
#pragma unroll
            for (int mt = 0; mt < 2; ++mt) {
                int R = wm * 32 + mt * 16 + g;
                tsplit(As[kk + t][R],       ah[mt][0], al[mt][0]);
                tsplit(As[kk + t][R + 8],   ah[mt][1], al[mt][1]);
                tsplit(As[kk + t + 4][R],     ah[mt][2], al[mt][2]);
                tsplit(As[kk + t + 4][R + 8], ah[mt][3], al[mt][3]);
            }
#pragma unroll
            for (int nt = 0; nt < 4; ++nt) {
                int NN = wn * 32 + nt * 8 + g;
                unsigned qh[2], ql[2], mh[2], ml[2];
                tsplit(Bq[kk + t][NN],     qh[0], ql[0]);
                tsplit(Bq[kk + t + 4][NN], qh[1], ql[1]);
                tsplit(Bm[kk + t][NN],     mh[0], ml[0]);
                tsplit(Bm[kk + t + 4][NN], mh[1], ml[1]);
#pragma unroll
                for (int mt = 0; mt < 2; ++mt) {
                    mma8(accA[mt][nt], ah[mt], qh);
                    mma8(accA[mt][nt], al[mt], qh);
                    mma8(accA[mt][nt], ah[mt], ql);
                    mma8(accB[mt][nt], ah[mt], mh);
                    mma8(accB[mt][nt], al[mt], mh);
                    mma8(accB[mt][nt], ah[mt], ml);
                }
            }
        }
    }

    // ---- epilogue: divide by rowsum, write 4 channels ----
    size_t ob = (size_t)b * 4 * D * LC;
#pragma unroll
    for (int mt = 0; mt < 2; ++mt)
#pragma unroll
        for (int half = 0; half < 2; ++half) {
            int rl = wm * 32 + mt * 16 + g + 8 * half;
            int ii = i0 + rl;
            float rv = 1.0f / g_rowsum[b * LC + ii];
#pragma unroll
            for (int nt = 0; nt < 4; ++nt) {
#pragma unroll
                for (int par = 0; par < 2; ++par) {
                    int dd = dd0 + wn * 32 + nt * 8 + 2 * t + par;
                    float a  = accA[mt][nt][half * 2 + par] * rv;
                    float bm = accB[mt][nt][half * 2 + par] * rv;
                    float cv = Cb[(size_t)dd * LC + ii];
                    out[ob + (size_t)dd * LC + ii] = cv;
                    out[ob + (size_t)(D + dd) * LC + ii] = a;
                    out[ob + (size_t)(2 * D + dd) * LC + ii] = cv * a;
                    out[ob + (size_t)(3 * D + dd) * LC + ii] = cv * bm;
                }
            }
        }
}

// ---------------- launch ------------------------------------------------------
extern "C" void kernel_launch(void* const* d_in, const int* in_sizes, int n_in,
                              void* d_out, int out_size) {
    const float* C = (const float*)d_in[0];
    const float* Q = (const float*)d_in[1];
    const float* cmask = (const float*)d_in[2];
    const float* qmask = (const float*)d_in[3];
    const float* w = (const float*)d_in[4];
    float* out = (float*)d_out;

    k0_setup<<<(B * LC + B * LQ) / 256, 256>>>(C, Q, cmask, qmask, w);

    dim3 g1(LQ / 128, LC / 128, B);
    k1_score<<<g1, 256>>>(C, Q, w);

    dim3 g4(LQ / 128, B);
    k4_m<<<g4, 256>>>(C);

    dim3 g5(D / 64, LC / 128, B);
    k5_out<<<g5, 256>>>(C, Q, out);
}

// round 7
// speedup vs baseline: 1.8332x; 1.4988x over previous
#include <cuda_runtime.h>
#include <math.h>

#define B    64
#define D    128
#define LC   1024
#define LQ   256
#define NEG_INF -1e30f
#define SA   132     // smem row stride for 128-wide tiles (132%32==4 -> conflict-free frags)
#define SB   68      // smem row stride for 64-wide tiles  (68%32==4)

// ---------------- scratch (device globals: no allocation allowed) ----------------
__device__ float g_E[(size_t)B * LC * LQ];   // exp(S), 64 MiB
__device__ float g_M[(size_t)B * LQ * D];    // S2^T @ Ct (already / colsum)
__device__ float g_rowsum[B * LC];
__device__ float g_colsum[B * LQ];
__device__ float g_cw1[B * LC];
__device__ float g_qw2[B * LQ];
__device__ float g_fc[B * LC];               // exp((1-cmask)*NEG_INF)  (0 or 1)
__device__ float g_fq[B * LQ];               // exp((1-qmask)*NEG_INF)

// ---------------- tf32 helpers ----------------
__device__ __forceinline__ unsigned f2t(float x) {
    unsigned u; asm("cvt.rna.tf32.f32 %0, %1;" : "=r"(u) : "f"(x)); return u;
}
__device__ __forceinline__ uint4 f2t4(float4 v) {
    return make_uint4(f2t(v.x), f2t(v.y), f2t(v.z), f2t(v.w));
}
// D += A(16x8) * B(8x8), tf32 inputs, f32 accum
__device__ __forceinline__ void mma8(float* c, const unsigned* a, const unsigned* b) {
    asm volatile(
        "mma.sync.aligned.m16n8k8.row.col.f32.tf32.tf32.f32 "
        "{%0,%1,%2,%3},{%4,%5,%6,%7},{%8,%9},{%0,%1,%2,%3};"
        : "+f"(c[0]), "+f"(c[1]), "+f"(c[2]), "+f"(c[3])
        : "r"(a[0]), "r"(a[1]), "r"(a[2]), "r"(a[3]), "r"(b[0]), "r"(b[1]));
}

// ---------------- K0: biases, mask factors, zero accumulators ----------------
__global__ void k0_setup(const float* __restrict__ C, const float* __restrict__ Q,
                         const float* __restrict__ cmask, const float* __restrict__ qmask,
                         const float* __restrict__ w) {
    int idx = blockIdx.x * 256 + threadIdx.x;
    if (idx < B * LC) {
        int b = idx >> 10;
        int i = idx & (LC - 1);
        const float* cp = C + (size_t)b * D * LC + i;
        float s = 0.f;
#pragma unroll 4
        for (int dd = 0; dd < D; ++dd) s = fmaf(cp[(size_t)dd * LC], w[dd], s);
        g_cw1[idx] = s;
        g_fc[idx] = expf((1.0f - cmask[idx]) * NEG_INF);
        g_rowsum[idx] = 0.f;
    } else {
        int t = idx - B * LC;
        if (t < B * LQ) {
            int b = t >> 8;
            int j = t & (LQ - 1);
            const float* qp = Q + (size_t)b * D * LQ + j;
            float s = 0.f;
#pragma unroll 4
            for (int dd = 0; dd < D; ++dd) s = fmaf(qp[(size_t)dd * LQ], w[D + dd], s);
            g_qw2[t] = s;
            g_fq[t] = expf((1.0f - qmask[t]) * NEG_INF);
            g_colsum[t] = 0.f;
        }
    }
}

// ---------------- K1: E = exp(S) + row/col exp-sums (single-tf32 MMA) --------
// grid (LQ/128, LC/128, B), 256 thr.  M=i(128) N=j(128) K=d(128)
__global__ __launch_bounds__(256) void k1_score(const float* __restrict__ C,
                                                const float* __restrict__ Q,
                                                const float* __restrict__ w) {
    int b = blockIdx.z, i0 = blockIdx.y * 128, j0 = blockIdx.x * 128;

    __shared__ unsigned As[32][SA];   // [k=d][m=i]  tf32(C*w3)
    __shared__ unsigned Bs[32][SA];   // [k=d][n=j]  tf32(Q)
    __shared__ float scw[128], sfcs[128], sqw[128], sfqs[128], srow[128], scol[128];

    int tid = threadIdx.x;
    int wid = tid >> 5, lane = tid & 31, g = lane >> 2, t = lane & 3;
    int wm = wid & 3, wn = wid >> 2;     // warp tile: 32(m) x 64(n)

    float acc[2][8][4];
#pragma unroll
    for (int mt = 0; mt < 2; ++mt)
#pragma unroll
        for (int nt = 0; nt < 8; ++nt)
#pragma unroll
            for (int c = 0; c < 4; ++c) acc[mt][nt][c] = 0.f;

    const float* Cb = C + (size_t)b * D * LC;
    const float* Qb = Q + (size_t)b * D * LQ;

    int qm = tid & 31, kr = tid >> 5;    // loader: m-quad, k-row

    uint4 pa[4], pb[4];
#pragma unroll
    for (int p = 0; p < 4; ++p) {        // prefetch chunk 0 (convert at load)
        int k = kr + 8 * p;
        float w3 = w[2 * D + k];
        float4 v = *(const float4*)(Cb + (size_t)k * LC + i0 + 4 * qm);
        v.x *= w3; v.y *= w3; v.z *= w3; v.w *= w3;
        pa[p] = f2t4(v);
        pb[p] = f2t4(*(const float4*)(Qb + (size_t)k * LQ + j0 + 4 * qm));
    }

    for (int kc = 0; kc < D; kc += 32) {
        __syncthreads();
#pragma unroll
        for (int p = 0; p < 4; ++p) {
            *(uint4*)&As[kr + 8 * p][4 * qm] = pa[p];
            *(uint4*)&Bs[kr + 8 * p][4 * qm] = pb[p];
        }
        __syncthreads();
        if (kc + 32 < D) {
#pragma unroll
            for (int p = 0; p < 4; ++p) {
                int k = kc + 32 + kr + 8 * p;
                float w3 = w[2 * D + k];
                float4 v = *(const float4*)(Cb + (size_t)k * LC + i0 + 4 * qm);
                v.x *= w3; v.y *= w3; v.z *= w3; v.w *= w3;
                pa[p] = f2t4(v);
                pb[p] = f2t4(*(const float4*)(Qb + (size_t)k * LQ + j0 + 4 * qm));
            }
        }
#pragma unroll
        for (int k8 = 0; k8 < 4; ++k8) {
            int kk = 8 * k8;
            unsigned a[2][4];
#pragma unroll
            for (int mt = 0; mt < 2; ++mt) {
                int R = wm * 32 + mt * 16 + g;
                a[mt][0] = As[kk + t][R];
                a[mt][1] = As[kk + t][R + 8];
                a[mt][2] = As[kk + t + 4][R];
                a[mt][3] = As[kk + t + 4][R + 8];
            }
#pragma unroll
            for (int nt = 0; nt < 8; ++nt) {
                int NN = wn * 64 + nt * 8 + g;
                unsigned bb[2] = { Bs[kk + t][NN], Bs[kk + t + 4][NN] };
#pragma unroll
                for (int mt = 0; mt < 2; ++mt) mma8(acc[mt][nt], a[mt], bb);
            }
        }
    }

    // ---- epilogue ----
    __syncthreads();
    if (tid < 128) {
        scw[tid]  = g_cw1[b * LC + i0 + tid];
        sfcs[tid] = g_fc[b * LC + i0 + tid];
        srow[tid] = 0.f;
    } else {
        int j = tid - 128;
        sqw[j]  = g_qw2[b * LQ + j0 + j];
        sfqs[j] = g_fq[b * LQ + j0 + j];
        scol[j] = 0.f;
    }
    __syncthreads();

    float rowp[4] = {0.f, 0.f, 0.f, 0.f};
    float colp[16];
#pragma unroll
    for (int c = 0; c < 16; ++c) colp[c] = 0.f;

#pragma unroll
    for (int mt = 0; mt < 2; ++mt)
#pragma unroll
        for (int half = 0; half < 2; ++half) {
            int rl = wm * 32 + mt * 16 + g + 8 * half;
            float cwv = scw[rl], fcv = sfcs[rl];
#pragma unroll
            for (int nt = 0; nt < 8; ++nt) {
                int cl = wn * 64 + nt * 8 + 2 * t;
                float e0 = expf(acc[mt][nt][half * 2 + 0] + cwv + sqw[cl]);
                float e1 = expf(acc[mt][nt][half * 2 + 1] + cwv + sqw[cl + 1]);
                *(float2*)(g_E + ((size_t)b * LC + i0 + rl) * LQ + j0 + cl) =
                    make_float2(e0, e1);
                rowp[mt * 2 + half] += e0 * sfqs[cl] + e1 * sfqs[cl + 1];
                colp[nt * 2 + 0] += e0 * fcv;
                colp[nt * 2 + 1] += e1 * fcv;
            }
        }

#pragma unroll
    for (int r = 0; r < 4; ++r) {
        rowp[r] += __shfl_xor_sync(0xffffffffu, rowp[r], 1);
        rowp[r] += __shfl_xor_sync(0xffffffffu, rowp[r], 2);
    }
    if (t == 0) {
#pragma unroll
        for (int mt = 0; mt < 2; ++mt)
#pragma unroll
            for (int half = 0; half < 2; ++half)
                atomicAdd(&srow[wm * 32 + mt * 16 + g + 8 * half], rowp[mt * 2 + half]);
    }
#pragma unroll
    for (int c = 0; c < 16; ++c) {
        colp[c] += __shfl_xor_sync(0xffffffffu, colp[c], 4);
        colp[c] += __shfl_xor_sync(0xffffffffu, colp[c], 8);
        colp[c] += __shfl_xor_sync(0xffffffffu, colp[c], 16);
    }
    if (g == 0) {
#pragma unroll
        for (int nt = 0; nt < 8; ++nt)
#pragma unroll
            for (int par = 0; par < 2; ++par)
                atomicAdd(&scol[wn * 64 + nt * 8 + 2 * t + par], colp[nt * 2 + par]);
    }
    __syncthreads();
    if (tid < 128) atomicAdd(&g_rowsum[b * LC + i0 + tid], srow[tid]);
    else           atomicAdd(&g_colsum[b * LQ + j0 + tid - 128], scol[tid - 128]);
}

// ---------------- K4: M[j][dd] = (sum_i E[i][j]*fc[i]*C[dd][i]) / colsum[j] --
// grid (LQ/128, B), 256 thr.  M=j(128) N=dd(128) K=i(1024)
__global__ __launch_bounds__(256) void k4_m(const float* __restrict__ C) {
    int b = blockIdx.y, j0 = blockIdx.x * 128;

    __shared__ unsigned As[32][SA];   // [k=i][m=j]   tf32(E*fc)
    __shared__ unsigned Bs[32][SA];   // [k=i][n=dd]  tf32(C^T)

    int tid = threadIdx.x;
    int wid = tid >> 5, lane = tid & 31, g = lane >> 2, t = lane & 3;
    int wm = wid & 3, wn = wid >> 2;

    float acc[2][8][4];
#pragma unroll
    for (int mt = 0; mt < 2; ++mt)
#pragma unroll
        for (int nt = 0; nt < 8; ++nt)
#pragma unroll
            for (int c = 0; c < 4; ++c) acc[mt][nt][c] = 0.f;

    const float* Cb = C + (size_t)b * D * LC;
    const float* Eb = g_E + (size_t)b * LC * LQ;

    int qm = tid & 31, kr = tid >> 5;     // A loader
    int dd = tid & 127, kq = tid >> 7;    // B loader (transpose)

    uint4 va[4], vb[4];
#pragma unroll
    for (int p = 0; p < 4; ++p) {
        int i = kr + 8 * p;
        float f = g_fc[b * LC + i];
        float4 v = *(const float4*)(Eb + (size_t)i * LQ + j0 + 4 * qm);
        v.x *= f; v.y *= f; v.z *= f; v.w *= f;
        va[p] = f2t4(v);
        vb[p] = f2t4(*(const float4*)(Cb + (size_t)dd * LC + 4 * (kq + 2 * p)));
    }

    for (int kc = 0; kc < LC; kc += 32) {
        __syncthreads();
#pragma unroll
        for (int p = 0; p < 4; ++p) {
            *(uint4*)&As[kr + 8 * p][4 * qm] = va[p];
            int kb = 4 * (kq + 2 * p);
            Bs[kb + 0][dd] = vb[p].x;
            Bs[kb + 1][dd] = vb[p].y;
            Bs[kb + 2][dd] = vb[p].z;
            Bs[kb + 3][dd] = vb[p].w;
        }
        __syncthreads();
        if (kc + 32 < LC) {
#pragma unroll
            for (int p = 0; p < 4; ++p) {
                int i = kc + 32 + kr + 8 * p;
                float f = g_fc[b * LC + i];
                float4 v = *(const float4*)(Eb + (size_t)i * LQ + j0 + 4 * qm);
                v.x *= f; v.y *= f; v.z *= f; v.w *= f;
                va[p] = f2t4(v);
                vb[p] = f2t4(*(const float4*)(Cb + (size_t)dd * LC + kc + 32 + 4 * (kq + 2 * p)));
            }
        }
#pragma unroll
        for (int k8 = 0; k8 < 4; ++k8) {
            int kk = 8 * k8;
            unsigned a[2][4];
#pragma unroll
            for (int mt = 0; mt < 2; ++mt) {
                int R = wm * 32 + mt * 16 + g;
                a[mt][0] = As[kk + t][R];
                a[mt][1] = As[kk + t][R + 8];
                a[mt][2] = As[kk + t + 4][R];
                a[mt][3] = As[kk + t + 4][R + 8];
            }
#pragma unroll
            for (int nt = 0; nt < 8; ++nt) {
                int NN = wn * 64 + nt * 8 + g;
                unsigned bb[2] = { Bs[kk + t][NN], Bs[kk + t + 4][NN] };
#pragma unroll
                for (int mt = 0; mt < 2; ++mt) mma8(acc[mt][nt], a[mt], bb);
            }
        }
    }

    // ---- epilogue: divide by colsum, store M ----
#pragma unroll
    for (int mt = 0; mt < 2; ++mt)
#pragma unroll
        for (int half = 0; half < 2; ++half) {
            int rl = wm * 32 + mt * 16 + g + 8 * half;
            int jj = j0 + rl;
            float ci = 1.0f / g_colsum[b * LQ + jj];
#pragma unroll
            for (int nt = 0; nt < 8; ++nt) {
                int ddc = wn * 64 + nt * 8 + 2 * t;
                *(float2*)(g_M + ((size_t)b * LQ + jj) * D + ddc) =
                    make_float2(acc[mt][nt][half * 2 + 0] * ci,
                                acc[mt][nt][half * 2 + 1] * ci);
            }
        }
}

// ---------------- K5: A & Bmat (dual GEMM) + 4 output channels ----------------
// grid (D/64, LC/128, B), 256 thr.  M=i(128) N=dd(64) K=j(256)
__global__ __launch_bounds__(256) void k5_out(const float* __restrict__ C,
                                              const float* __restrict__ Q,
                                              float* __restrict__ out) {
    int b = blockIdx.z, i0 = blockIdx.y * 128, dd0 = blockIdx.x * 64;

    __shared__ unsigned As[32][SA];   // [k=j][m=i]   tf32(E*fq)
    __shared__ unsigned Bq[32][SB];   // [k=j][n=dd]  tf32(Q^T)
    __shared__ unsigned Bm[32][SB];   // [k=j][n=dd]  tf32(M)
    __shared__ float sfq[LQ];

    int tid = threadIdx.x;
    int wid = tid >> 5, lane = tid & 31, g = lane >> 2, t = lane & 3;
    int wm = wid & 3, wn = wid >> 2;     // warp tile: 32(m) x 32(n)

    sfq[tid] = g_fq[b * LQ + tid];

    float accA[2][4][4], accB[2][4][4];
#pragma unroll
    for (int mt = 0; mt < 2; ++mt)
#pragma unroll
        for (int nt = 0; nt < 4; ++nt)
#pragma unroll
            for (int c = 0; c < 4; ++c) { accA[mt][nt][c] = 0.f; accB[mt][nt][c] = 0.f; }

    const float* Cb = C + (size_t)b * D * LC;
    const float* Qb = Q + (size_t)b * D * LQ;
    const float* Eb = g_E + (size_t)b * LC * LQ;
    const float* Mb = g_M + (size_t)b * LQ * D;

    int ia = tid & 127, kqa = tid >> 7;        // A loader (transpose)
    int dq = tid & 63,  kq2 = (tid >> 6) & 3;  // Bq loader (transpose)
    int qn = tid & 15,  krm = tid >> 4;        // Bm loader (direct)

    float4 ea[4];
    uint4 qa[2], ma[2];
#pragma unroll
    for (int p = 0; p < 4; ++p)
        ea[p] = *(const float4*)(Eb + (size_t)(i0 + ia) * LQ + 4 * (kqa + 2 * p));
#pragma unroll
    for (int p = 0; p < 2; ++p) {
        qa[p] = f2t4(*(const float4*)(Qb + (size_t)(dd0 + dq) * LQ + 4 * (kq2 + 4 * p)));
        ma[p] = f2t4(*(const float4*)(Mb + (size_t)(krm + 16 * p) * D + dd0 + 4 * qn));
    }

    for (int kc = 0; kc < LQ; kc += 32) {
        __syncthreads();
#pragma unroll
        for (int p = 0; p < 4; ++p) {
            int ka = 4 * (kqa + 2 * p);
            As[ka + 0][ia] = f2t(ea[p].x * sfq[kc + ka + 0]);
            As[ka + 1][ia] = f2t(ea[p].y * sfq[kc + ka + 1]);
            As[ka + 2][ia] = f2t(ea[p].z * sfq[kc + ka + 2]);
            As[ka + 3][ia] = f2t(ea[p].w * sfq[kc + ka + 3]);
        }
#pragma unroll
        for (int p = 0; p < 2; ++p) {
            int kb = 4 * (kq2 + 4 * p);
            Bq[kb + 0][dq] = qa[p].x;
            Bq[kb + 1][dq] = qa[p].y;
            Bq[kb + 2][dq] = qa[p].z;
            Bq[kb + 3][dq] = qa[p].w;
            *(uint4*)&Bm[krm + 16 * p][4 * qn] = ma[p];
        }
        __syncthreads();
        if (kc + 32 < LQ) {
#pragma unroll
            for (int p = 0; p < 4; ++p)
                ea[p] = *(const float4*)(Eb + (size_t)(i0 + ia) * LQ + kc + 32 + 4 * (kqa + 2 * p));
#pragma unroll
            for (int p = 0; p < 2; ++p) {
                qa[p] = f2t4(*(const float4*)(Qb + (size_t)(dd0 + dq) * LQ + kc + 32 + 4 * (kq2 + 4 * p)));
                ma[p] = f2t4(*(const float4*)(Mb + (size_t)(kc + 32 + krm + 16 * p) * D + dd0 + 4 * qn));
            }
        }
#pragma unroll
        for (int k8 = 0; k8 < 4; ++k8) {
            int kk = 8 * k8;
            unsigned a[2][4];
#pragma unroll
            for (int mt = 0; mt < 2; ++mt) {
                int R = wm * 32 + mt * 16 + g;
                a[mt][0] = As[kk + t][R];
                a[mt][1] = As[kk + t][R + 8];
                a[mt][2] = As[kk + t + 4][R];
                a[mt][3] = As[kk + t + 4][R + 8];
            }
#pragma unroll
            for (int nt = 0; nt < 4; ++nt) {
                int NN = wn * 32 + nt * 8 + g;
                unsigned bq[2] = { Bq[kk + t][NN], Bq[kk + t + 4][NN] };
                unsigned bm[2] = { Bm[kk + t][NN], Bm[kk + t + 4][NN] };
#pragma unroll
                for (int mt = 0; mt < 2; ++mt) {
                    mma8(accA[mt][nt], a[mt], bq);
                    mma8(accB[mt][nt], a[mt], bm);
                }
            }
        }
    }

    // ---- epilogue: divide by rowsum, write 4 channels ----
    size_t ob = (size_t)b * 4 * D * LC;
#pragma unroll
    for (int mt = 0; mt < 2; ++mt)
#pragma unroll
        for (int half = 0; half < 2; ++half) {
            int rl = wm * 32 + mt * 16 + g + 8 * half;
            int ii = i0 + rl;
            float rv = 1.0f / g_rowsum[b * LC + ii];
#pragma unroll
            for (int nt = 0; nt < 4; ++nt) {
#pragma unroll
                for (int par = 0; par < 2; ++par) {
                    int dd = dd0 + wn * 32 + nt * 8 + 2 * t + par;
                    float a  = accA[mt][nt][half * 2 + par] * rv;
                    float bm = accB[mt][nt][half * 2 + par] * rv;
                    float cv = Cb[(size_t)dd * LC + ii];
                    out[ob + (size_t)dd * LC + ii] = cv;
                    out[ob + (size_t)(D + dd) * LC + ii] = a;
                    out[ob + (size_t)(2 * D + dd) * LC + ii] = cv * a;
                    out[ob + (size_t)(3 * D + dd) * LC + ii] = cv * bm;
                }
            }
        }
}

// ---------------- launch ------------------------------------------------------
extern "C" void kernel_launch(void* const* d_in, const int* in_sizes, int n_in,
                              void* d_out, int out_size) {
    const float* C = (const float*)d_in[0];
    const float* Q = (const float*)d_in[1];
    const float* cmask = (const float*)d_in[2];
    const float* qmask = (const float*)d_in[3];
    const float* w = (const float*)d_in[4];
    float* out = (float*)d_out;

    k0_setup<<<(B * LC + B * LQ) / 256, 256>>>(C, Q, cmask, qmask, w);

    dim3 g1(LQ / 128, LC / 128, B);
    k1_score<<<g1, 256>>>(C, Q, w);

    dim3 g4(LQ / 128, B);
    k4_m<<<g4, 256>>>(C);

    dim3 g5(D / 64, LC / 128, B);
    k5_out<<<g5, 256>>>(C, Q, out);
}

// round 8
// speedup vs baseline: 1.8334x; 1.0001x over previous
#include <cuda_runtime.h>
#include <math.h>

#define B    64
#define D    128
#define LC   1024
#define LQ   256
#define NEG_INF -1e30f
#define SA   132     // smem row stride (132%32==4 -> conflict-free frags)
#define SB   68      // smem row stride for 64-wide tiles  (68%32==4)

// ---------------- scratch (device globals: no allocation allowed) ----------------
__device__ float g_E[(size_t)B * LC * LQ];   // exp(S), 64 MiB
__device__ float g_M[(size_t)B * LQ * D];    // S2^T @ Ct (already / colsum)
__device__ float g_rowsum[B * LC];
__device__ float g_colsum[B * LQ];
__device__ float g_cw1[B * LC];
__device__ float g_qw2[B * LQ];
__device__ float g_fc[B * LC];               // exp((1-cmask)*NEG_INF)  (0 or 1)
__device__ float g_fq[B * LQ];               // exp((1-qmask)*NEG_INF)

// ---------------- tf32 helpers ----------------
__device__ __forceinline__ unsigned f2t(float x) {
    unsigned u; asm("cvt.rna.tf32.f32 %0, %1;" : "=r"(u) : "f"(x)); return u;
}
__device__ __forceinline__ uint4 f2t4(float4 v) {
    return make_uint4(f2t(v.x), f2t(v.y), f2t(v.z), f2t(v.w));
}
__device__ __forceinline__ void mma8(float* c, const unsigned* a, const unsigned* b) {
    asm volatile(
        "mma.sync.aligned.m16n8k8.row.col.f32.tf32.tf32.f32 "
        "{%0,%1,%2,%3},{%4,%5,%6,%7},{%8,%9},{%0,%1,%2,%3};"
        : "+f"(c[0]), "+f"(c[1]), "+f"(c[2]), "+f"(c[3])
        : "r"(a[0]), "r"(a[1]), "r"(a[2]), "r"(a[3]), "r"(b[0]), "r"(b[1]));
}

// ---------------- K0: biases, mask factors, zero accumulators ----------------
__global__ void k0_setup(const float* __restrict__ C, const float* __restrict__ Q,
                         const float* __restrict__ cmask, const float* __restrict__ qmask,
                         const float* __restrict__ w) {
    int idx = blockIdx.x * 256 + threadIdx.x;
    if (idx < B * LC) {
        int b = idx >> 10;
        int i = idx & (LC - 1);
        const float* cp = C + (size_t)b * D * LC + i;
        float s = 0.f;
#pragma unroll 4
        for (int dd = 0; dd < D; ++dd) s = fmaf(cp[(size_t)dd * LC], w[dd], s);
        g_cw1[idx] = s;
        g_fc[idx] = __expf((1.0f - cmask[idx]) * NEG_INF);
        g_rowsum[idx] = 0.f;
    } else {
        int t = idx - B * LC;
        if (t < B * LQ) {
            int b = t >> 8;
            int j = t & (LQ - 1);
            const float* qp = Q + (size_t)b * D * LQ + j;
            float s = 0.f;
#pragma unroll 4
            for (int dd = 0; dd < D; ++dd) s = fmaf(qp[(size_t)dd * LQ], w[D + dd], s);
            g_qw2[t] = s;
            g_fq[t] = __expf((1.0f - qmask[t]) * NEG_INF);
            g_colsum[t] = 0.f;
        }
    }
}

// ---------------- K1: E = exp(S) + row/col exp-sums (tf32 MMA) ---------------
// grid (LQ/128, LC/128, B), 256 thr.  M=i(128) N=j(128) K=d(128)
__global__ __launch_bounds__(256, 2) void k1_score(const float* __restrict__ C,
                                                   const float* __restrict__ Q,
                                                   const float* __restrict__ w) {
    int b = blockIdx.z, i0 = blockIdx.y * 128, j0 = blockIdx.x * 128;

    __shared__ __align__(16) unsigned SMB[2 * 32 * SA];   // As|Bs; reused as tr[64][SA]
    unsigned (*As)[SA] = (unsigned(*)[SA])SMB;
    unsigned (*Bs)[SA] = (unsigned(*)[SA])(SMB + 32 * SA);
    float* tr = (float*)SMB;
    __shared__ float scw[128], sfcs[128], sqw[128], sfqs[128], srow[128], scol[128];

    int tid = threadIdx.x;
    int wid = tid >> 5, lane = tid & 31, g = lane >> 2, t = lane & 3;
    int wm = wid & 3, wn = wid >> 2;     // warp tile: 32(m) x 64(n)

    float acc[2][8][4];
#pragma unroll
    for (int mt = 0; mt < 2; ++mt)
#pragma unroll
        for (int nt = 0; nt < 8; ++nt)
#pragma unroll
            for (int c = 0; c < 4; ++c) acc[mt][nt][c] = 0.f;

    const float* Cb = C + (size_t)b * D * LC;
    const float* Qb = Q + (size_t)b * D * LQ;

    int qm = tid & 31, kr = tid >> 5;    // loader: m-quad, k-row

    uint4 pa[4], pb[4];
#pragma unroll
    for (int p = 0; p < 4; ++p) {        // prefetch chunk 0
        int k = kr + 8 * p;
        float w3 = w[2 * D + k];
        float4 v = *(const float4*)(Cb + (size_t)k * LC + i0 + 4 * qm);
        v.x *= w3; v.y *= w3; v.z *= w3; v.w *= w3;
        pa[p] = f2t4(v);
        pb[p] = f2t4(*(const float4*)(Qb + (size_t)k * LQ + j0 + 4 * qm));
    }

    for (int kc = 0; kc < D; kc += 32) {
        __syncthreads();
#pragma unroll
        for (int p = 0; p < 4; ++p) {
            *(uint4*)&As[kr + 8 * p][4 * qm] = pa[p];
            *(uint4*)&Bs[kr + 8 * p][4 * qm] = pb[p];
        }
        __syncthreads();
        if (kc + 32 < D) {
#pragma unroll
            for (int p = 0; p < 4; ++p) {
                int k = kc + 32 + kr + 8 * p;
                float w3 = w[2 * D + k];
                float4 v = *(const float4*)(Cb + (size_t)k * LC + i0 + 4 * qm);
                v.x *= w3; v.y *= w3; v.z *= w3; v.w *= w3;
                pa[p] = f2t4(v);
                pb[p] = f2t4(*(const float4*)(Qb + (size_t)k * LQ + j0 + 4 * qm));
            }
        }
#pragma unroll
        for (int k8 = 0; k8 < 4; ++k8) {
            int kk = 8 * k8;
            unsigned a[2][4];
#pragma unroll
            for (int mt = 0; mt < 2; ++mt) {
                int R = wm * 32 + mt * 16 + g;
                a[mt][0] = As[kk + t][R];
                a[mt][1] = As[kk + t][R + 8];
                a[mt][2] = As[kk + t + 4][R];
                a[mt][3] = As[kk + t + 4][R + 8];
            }
#pragma unroll
            for (int nt = 0; nt < 8; ++nt) {
                int NN = wn * 64 + nt * 8 + g;
                unsigned bb[2] = { Bs[kk + t][NN], Bs[kk + t + 4][NN] };
#pragma unroll
                for (int mt = 0; mt < 2; ++mt) mma8(acc[mt][nt], a[mt], bb);
            }
        }
    }

    // ---- epilogue: exp into acc, row/col partial sums ----
    __syncthreads();
    if (tid < 128) {
        scw[tid]  = g_cw1[b * LC + i0 + tid];
        sfcs[tid] = g_fc[b * LC + i0 + tid];
        srow[tid] = 0.f;
    } else {
        int j = tid - 128;
        sqw[j]  = g_qw2[b * LQ + j0 + j];
        sfqs[j] = g_fq[b * LQ + j0 + j];
        scol[j] = 0.f;
    }
    __syncthreads();

    float rowp[4] = {0.f, 0.f, 0.f, 0.f};
    float colp[16];
#pragma unroll
    for (int c = 0; c < 16; ++c) colp[c] = 0.f;

#pragma unroll
    for (int mt = 0; mt < 2; ++mt)
#pragma unroll
        for (int half = 0; half < 2; ++half) {
            int rl = wm * 32 + mt * 16 + g + 8 * half;
            float cwv = scw[rl], fcv = sfcs[rl];
#pragma unroll
            for (int nt = 0; nt < 8; ++nt) {
                int cl = wn * 64 + nt * 8 + 2 * t;
                float e0 = __expf(acc[mt][nt][half * 2 + 0] + cwv + sqw[cl]);
                float e1 = __expf(acc[mt][nt][half * 2 + 1] + cwv + sqw[cl + 1]);
                acc[mt][nt][half * 2 + 0] = e0;
                acc[mt][nt][half * 2 + 1] = e1;
                rowp[mt * 2 + half] += e0 * sfqs[cl] + e1 * sfqs[cl + 1];
                colp[nt * 2 + 0] += e0 * fcv;
                colp[nt * 2 + 1] += e1 * fcv;
            }
        }

#pragma unroll
    for (int r = 0; r < 4; ++r) {
        rowp[r] += __shfl_xor_sync(0xffffffffu, rowp[r], 1);
        rowp[r] += __shfl_xor_sync(0xffffffffu, rowp[r], 2);
    }
    if (t == 0) {
#pragma unroll
        for (int mt = 0; mt < 2; ++mt)
#pragma unroll
            for (int half = 0; half < 2; ++half)
                atomicAdd(&srow[wm * 32 + mt * 16 + g + 8 * half], rowp[mt * 2 + half]);
    }
#pragma unroll
    for (int c = 0; c < 16; ++c) {
        colp[c] += __shfl_xor_sync(0xffffffffu, colp[c], 4);
        colp[c] += __shfl_xor_sync(0xffffffffu, colp[c], 8);
        colp[c] += __shfl_xor_sync(0xffffffffu, colp[c], 16);
    }
    if (g == 0) {
#pragma unroll
        for (int nt = 0; nt < 8; ++nt)
#pragma unroll
            for (int par = 0; par < 2; ++par)
                atomicAdd(&scol[wn * 64 + nt * 8 + 2 * t + par], colp[nt * 2 + par]);
    }
    __syncthreads();
    if (tid < 128) atomicAdd(&g_rowsum[b * LC + i0 + tid], srow[tid]);
    else           atomicAdd(&g_colsum[b * LQ + j0 + tid - 128], scol[tid - 128]);

    // ---- coalesced E store via smem transpose (2 chunks of 64 rows) ----
    int r2 = tid >> 4, c16 = tid & 15;
#pragma unroll
    for (int ch = 0; ch < 2; ++ch) {
        __syncthreads();
        if ((wm >> 1) == ch) {
#pragma unroll
            for (int mt = 0; mt < 2; ++mt)
#pragma unroll
                for (int half = 0; half < 2; ++half) {
                    int rowl = (wm & 1) * 32 + mt * 16 + g + 8 * half;
#pragma unroll
                    for (int nt = 0; nt < 8; ++nt) {
                        int col = wn * 64 + nt * 8 + 2 * t;
                        tr[rowl * SA + col]     = acc[mt][nt][half * 2 + 0];
                        tr[rowl * SA + col + 1] = acc[mt][nt][half * 2 + 1];
                    }
                }
        }
        __syncthreads();
        float* dst = g_E + ((size_t)b * LC + i0 + ch * 64) * LQ + j0;
#pragma unroll
        for (int rr = 0; rr < 4; ++rr)
#pragma unroll
            for (int seg = 0; seg < 2; ++seg) {
                int row = r2 + 16 * rr;
                *(float4*)(dst + (size_t)row * LQ + seg * 64 + 4 * c16) =
                    *(float4*)&tr[row * SA + seg * 64 + 4 * c16];
            }
    }
}

// ---------------- K4: M[j][dd] = (sum_i E[i][j]*fc[i]*C[dd][i]) / colsum[j] --
// grid (LQ/128, B), 256 thr.  M=j(128) N=dd(128) K=i(1024)
__global__ __launch_bounds__(256, 2) void k4_m(const float* __restrict__ C) {
    int b = blockIdx.y, j0 = blockIdx.x * 128;

    __shared__ __align__(16) unsigned SMB[2 * 32 * SA];
    unsigned (*As)[SA] = (unsigned(*)[SA])SMB;
    unsigned (*Bs)[SA] = (unsigned(*)[SA])(SMB + 32 * SA);
    float* tr = (float*)SMB;

    int tid = threadIdx.x;
    int wid = tid >> 5, lane = tid & 31, g = lane >> 2, t = lane & 3;
    int wm = wid & 3, wn = wid >> 2;

    float acc[2][8][4];
#pragma unroll
    for (int mt = 0; mt < 2; ++mt)
#pragma unroll
        for (int nt = 0; nt < 8; ++nt)
#pragma unroll
            for (int c = 0; c < 4; ++c) acc[mt][nt][c] = 0.f;

    const float* Cb = C + (size_t)b * D * LC;
    const float* Eb = g_E + (size_t)b * LC * LQ;

    int qm = tid & 31, kr = tid >> 5;     // A loader
    int dd = tid & 127, kq = tid >> 7;    // B loader (transpose)

    uint4 va[4], vb[4];
#pragma unroll
    for (int p = 0; p < 4; ++p) {
        int i = kr + 8 * p;
        float f = g_fc[b * LC + i];
        float4 v = *(const float4*)(Eb + (size_t)i * LQ + j0 + 4 * qm);
        v.x *= f; v.y *= f; v.z *= f; v.w *= f;
        va[p] = f2t4(v);
        vb[p] = f2t4(*(const float4*)(Cb + (size_t)dd * LC + 4 * (kq + 2 * p)));
    }

    for (int kc = 0; kc < LC; kc += 32) {
        __syncthreads();
#pragma unroll
        for (int p = 0; p < 4; ++p) {
            *(uint4*)&As[kr + 8 * p][4 * qm] = va[p];
            int kb = 4 * (kq + 2 * p);
            Bs[kb + 0][dd] = vb[p].x;
            Bs[kb + 1][dd] = vb[p].y;
            Bs[kb + 2][dd] = vb[p].z;
            Bs[kb + 3][dd] = vb[p].w;
        }
        __syncthreads();
        if (kc + 32 < LC) {
#pragma unroll
            for (int p = 0; p < 4; ++p) {
                int i = kc + 32 + kr + 8 * p;
                float f = g_fc[b * LC + i];
                float4 v = *(const float4*)(Eb + (size_t)i * LQ + j0 + 4 * qm);
                v.x *= f; v.y *= f; v.z *= f; v.w *= f;
                va[p] = f2t4(v);
                vb[p] = f2t4(*(const float4*)(Cb + (size_t)dd * LC + kc + 32 + 4 * (kq + 2 * p)));
            }
        }
#pragma unroll
        for (int k8 = 0; k8 < 4; ++k8) {
            int kk = 8 * k8;
            unsigned a[2][4];
#pragma unroll
            for (int mt = 0; mt < 2; ++mt) {
                int R = wm * 32 + mt * 16 + g;
                a[mt][0] = As[kk + t][R];
                a[mt][1] = As[kk + t][R + 8];
                a[mt][2] = As[kk + t + 4][R];
                a[mt][3] = As[kk + t + 4][R + 8];
            }
#pragma unroll
            for (int nt = 0; nt < 8; ++nt) {
                int NN = wn * 64 + nt * 8 + g;
                unsigned bb[2] = { Bs[kk + t][NN], Bs[kk + t + 4][NN] };
#pragma unroll
                for (int mt = 0; mt < 2; ++mt) mma8(acc[mt][nt], a[mt], bb);
            }
        }
    }

    // ---- coalesced M store via smem transpose (2 chunks of 64 j-rows) ----
    int r2 = tid >> 4, c16 = tid & 15;
#pragma unroll
    for (int ch = 0; ch < 2; ++ch) {
        __syncthreads();
        if ((wm >> 1) == ch) {
#pragma unroll
            for (int mt = 0; mt < 2; ++mt)
#pragma unroll
                for (int half = 0; half < 2; ++half) {
                    int rowl = (wm & 1) * 32 + mt * 16 + g + 8 * half;
                    float ci = 1.0f / g_colsum[b * LQ + j0 + ch * 64 + rowl];
#pragma unroll
                    for (int nt = 0; nt < 8; ++nt) {
                        int col = wn * 64 + nt * 8 + 2 * t;
                        tr[rowl * SA + col]     = acc[mt][nt][half * 2 + 0] * ci;
                        tr[rowl * SA + col + 1] = acc[mt][nt][half * 2 + 1] * ci;
                    }
                }
        }
        __syncthreads();
        float* dst = g_M + ((size_t)b * LQ + j0 + ch * 64) * D;
#pragma unroll
        for (int rr = 0; rr < 4; ++rr)
#pragma unroll
            for (int seg = 0; seg < 2; ++seg) {
                int row = r2 + 16 * rr;
                *(float4*)(dst + (size_t)row * D + seg * 64 + 4 * c16) =
                    *(float4*)&tr[row * SA + seg * 64 + 4 * c16];
            }
    }
}

// ---------------- K5: A & Bmat (dual GEMM) + 4 output channels ----------------
// grid (D/64, LC/128, B), 256 thr.  M=i(128) N=dd(64) K=j(256)
__global__ __launch_bounds__(256, 2) void k5_out(const float* __restrict__ C,
                                                 const float* __restrict__ Q,
                                                 float* __restrict__ out) {
    int b = blockIdx.z, i0 = blockIdx.y * 128, dd0 = blockIdx.x * 64;

    __shared__ __align__(16) unsigned SMB[32 * SA + 2 * 32 * SB];  // As|Bq|Bm; tr[64][SA]
    unsigned (*As)[SA] = (unsigned(*)[SA])SMB;
    unsigned (*Bq)[SB] = (unsigned(*)[SB])(SMB + 32 * SA);
    unsigned (*Bm)[SB] = (unsigned(*)[SB])(SMB + 32 * SA + 32 * SB);
    float* tr = (float*)SMB;
    __shared__ float sfq[LQ];

    int tid = threadIdx.x;
    int wid = tid >> 5, lane = tid & 31, g = lane >> 2, t = lane & 3;
    int wm = wid & 3, wn = wid >> 2;     // warp tile: 32(m) x 32(n)

    sfq[tid] = g_fq[b * LQ + tid];

    float accA[2][4][4], accB[2][4][4];
#pragma unroll
    for (int mt = 0; mt < 2; ++mt)
#pragma unroll
        for (int nt = 0; nt < 4; ++nt)
#pragma unroll
            for (int c = 0; c < 4; ++c) { accA[mt][nt][c] = 0.f; accB[mt][nt][c] = 0.f; }

    const float* Cb = C + (size_t)b * D * LC;
    const float* Qb = Q + (size_t)b * D * LQ;
    const float* Eb = g_E + (size_t)b * LC * LQ;
    const float* Mb = g_M + (size_t)b * LQ * D;

    int ia = tid & 127, kqa = tid >> 7;        // A loader (transpose)
    int dq = tid & 63,  kq2 = (tid >> 6) & 3;  // Bq loader (transpose)
    int qn = tid & 15,  krm = tid >> 4;        // Bm loader (direct)

    float4 ea[4];
    uint4 qa[2], ma[2];
#pragma unroll
    for (int p = 0; p < 4; ++p)
        ea[p] = *(const float4*)(Eb + (size_t)(i0 + ia) * LQ + 4 * (kqa + 2 * p));
#pragma unroll
    for (int p = 0; p < 2; ++p) {
        qa[p] = f2t4(*(const float4*)(Qb + (size_t)(dd0 + dq) * LQ + 4 * (kq2 + 4 * p)));
        ma[p] = f2t4(*(const float4*)(Mb + (size_t)(krm + 16 * p) * D + dd0 + 4 * qn));
    }

    for (int kc = 0; kc < LQ; kc += 32) {
        __syncthreads();
#pragma unroll
        for (int p = 0; p < 4; ++p) {
            int ka = 4 * (kqa + 2 * p);
            As[ka + 0][ia] = f2t(ea[p].x * sfq[kc + ka + 0]);
            As[ka + 1][ia] = f2t(ea[p].y * sfq[kc + ka + 1]);
            As[ka + 2][ia] = f2t(ea[p].z * sfq[kc + ka + 2]);
            As[ka + 3][ia] = f2t(ea[p].w * sfq[kc + ka + 3]);
        }
#pragma unroll
        for (int p = 0; p < 2; ++p) {
            int kb = 4 * (kq2 + 4 * p);
            Bq[kb + 0][dq] = qa[p].x;
            Bq[kb + 1][dq] = qa[p].y;
            Bq[kb + 2][dq] = qa[p].z;
            Bq[kb + 3][dq] = qa[p].w;
            *(uint4*)&Bm[krm + 16 * p][4 * qn] = ma[p];
        }
        __syncthreads();
        if (kc + 32 < LQ) {
#pragma unroll
            for (int p = 0; p < 4; ++p)
                ea[p] = *(const float4*)(Eb + (size_t)(i0 + ia) * LQ + kc + 32 + 4 * (kqa + 2 * p));
#pragma unroll
            for (int p = 0; p < 2; ++p) {
                qa[p] = f2t4(*(const float4*)(Qb + (size_t)(dd0 + dq) * LQ + kc + 32 + 4 * (kq2 + 4 * p)));
                ma[p] = f2t4(*(const float4*)(Mb + (size_t)(kc + 32 + krm + 16 * p) * D + dd0 + 4 * qn));
            }
        }
#pragma unroll
        for (int k8 = 0; k8 < 4; ++k8) {
            int kk = 8 * k8;
            unsigned a[2][4];
#pragma unroll
            for (int mt = 0; mt < 2; ++mt) {
                int R = wm * 32 + mt * 16 + g;
                a[mt][0] = As[kk + t][R];
                a[mt][1] = As[kk + t][R + 8];
                a[mt][2] = As[kk + t + 4][R];
                a[mt][3] = As[kk + t + 4][R + 8];
            }
#pragma unroll
            for (int nt = 0; nt < 4; ++nt) {
                int NN = wn * 32 + nt * 8 + g;
                unsigned bq[2] = { Bq[kk + t][NN], Bq[kk + t + 4][NN] };
                unsigned bm[2] = { Bm[kk + t][NN], Bm[kk + t + 4][NN] };
#pragma unroll
                for (int mt = 0; mt < 2; ++mt) {
                    mma8(accA[mt][nt], a[mt], bq);
                    mma8(accB[mt][nt], a[mt], bm);
                }
            }
        }
    }

    // ---- epilogue: rowsum scale, transpose in smem, coalesced stores ----
    float rinv[2][2];
#pragma unroll
    for (int mt = 0; mt < 2; ++mt)
#pragma unroll
        for (int half = 0; half < 2; ++half)
            rinv[mt][half] = 1.0f / g_rowsum[b * LC + i0 + wm * 32 + mt * 16 + g + 8 * half];

    int r2 = tid >> 4, c16 = tid & 15;
    size_t ob = (size_t)b * 4 * D * LC;
    const float* Csrc = Cb + (size_t)dd0 * LC + i0;
    float* o0 = out + ob + (size_t)dd0 * LC + i0;

    // phase A: channels 0 (Ct), 1 (A), 2 (Ct*A)
    __syncthreads();
#pragma unroll
    for (int mt = 0; mt < 2; ++mt)
#pragma unroll
        for (int half = 0; half < 2; ++half) {
            int iil = wm * 32 + mt * 16 + g + 8 * half;
#pragma unroll
            for (int nt = 0; nt < 4; ++nt) {
                int ddl = wn * 32 + nt * 8 + 2 * t;
                tr[ddl * SA + iil]       = accA[mt][nt][half * 2 + 0] * rinv[mt][half];
                tr[(ddl + 1) * SA + iil] = accA[mt][nt][half * 2 + 1] * rinv[mt][half];
            }
        }
    __syncthreads();
#pragma unroll
    for (int rr = 0; rr < 4; ++rr)
#pragma unroll
        for (int seg = 0; seg < 2; ++seg) {
            int row = r2 + 16 * rr;
            int off = seg * 64 + 4 * c16;
            float4 a4 = *(float4*)&tr[row * SA + off];
            float4 c4 = *(const float4*)(Csrc + (size_t)row * LC + off);
            size_t go = (size_t)row * LC + off;
            *(float4*)(o0 + go) = c4;
            *(float4*)(o0 + (size_t)D * LC + go) = a4;
            *(float4*)(o0 + (size_t)2 * D * LC + go) =
                make_float4(c4.x * a4.x, c4.y * a4.y, c4.z * a4.z, c4.w * a4.w);
        }

    // phase B: channel 3 (Ct*Bmat)
    __syncthreads();
#pragma unroll
    for (int mt = 0; mt < 2; ++mt)
#pragma unroll
        for (int half = 0; half < 2; ++half) {
            int iil = wm * 32 + mt * 16 + g + 8 * half;
#pragma unroll
            for (int nt = 0; nt < 4; ++nt) {
                int ddl = wn * 32 + nt * 8 + 2 * t;
                tr[ddl * SA + iil]       = accB[mt][nt][half * 2 + 0] * rinv[mt][half];
                tr[(ddl + 1) * SA + iil] = accB[mt][nt][half * 2 + 1] * rinv[mt][half];
            }
        }
    __syncthreads();
#pragma unroll
    for (int rr = 0; rr < 4; ++rr)
#pragma unroll
        for (int seg = 0; seg < 2; ++seg) {
            int row = r2 + 16 * rr;
            int off = seg * 64 + 4 * c16;
            float4 b4 = *(float4*)&tr[row * SA + off];
            float4 c4 = *(const float4*)(Csrc + (size_t)row * LC + off);
            *(float4*)(o0 + (size_t)3 * D * LC + (size_t)row * LC + off) =
                make_float4(c4.x * b4.x, c4.y * b4.y, c4.z * b4.z, c4.w * b4.w);
        }
}

// ---------------- launch ------------------------------------------------------
extern "C" void kernel_launch(void* const* d_in, const int* in_sizes, int n_in,
                              void* d_out, int out_size) {
    const float* C = (const float*)d_in[0];
    const float* Q = (const float*)d_in[1];
    const float* cmask = (const float*)d_in[2];
    const float* qmask = (const float*)d_in[3];
    const float* w = (const float*)d_in[4];
    float* out = (float*)d_out;

    k0_setup<<<(B * LC + B * LQ) / 256, 256>>>(C, Q, cmask, qmask, w);

    dim3 g1(LQ / 128, LC / 128, B);
    k1_score<<<g1, 256>>>(C, Q, w);

    dim3 g4(LQ / 128, B);
    k4_m<<<g4, 256>>>(C);

    dim3 g5(D / 64, LC / 128, B);
    k5_out<<<g5, 256>>>(C, Q, out);
}

// round 9
// speedup vs baseline: 1.9953x; 1.0883x over previous
#include <cuda_runtime.h>
#include <math.h>

#define B    64
#define D    128
#define LC   1024
#define LQ   256
#define NEG_INF -1e30f
#define SA   136     // smem row stride (136%32==8 -> conflict-free fragment reads)
#define SB   72      // smem row stride for 64-wide tiles (72%32==8)

// ---------------- scratch (device globals: no allocation allowed) ----------------
__device__ float g_E[(size_t)B * LC * LQ];   // exp(S), 64 MiB
__device__ float g_M[(size_t)B * LQ * D];    // S2^T @ Ct (already / colsum)
__device__ float g_rowsum[B * LC];
__device__ float g_colsum[B * LQ];
__device__ float g_cw1[B * LC];
__device__ float g_qw2[B * LQ];
__device__ float g_fc[B * LC];               // exp((1-cmask)*NEG_INF)  (0 or 1)
__device__ float g_fq[B * LQ];               // exp((1-qmask)*NEG_INF)

// ---------------- tf32 helpers ----------------
__device__ __forceinline__ unsigned f2t(float x) {
    unsigned u; asm("cvt.rna.tf32.f32 %0, %1;" : "=r"(u) : "f"(x)); return u;
}
__device__ __forceinline__ uint4 f2t4(float4 v) {
    return make_uint4(f2t(v.x), f2t(v.y), f2t(v.z), f2t(v.w));
}
__device__ __forceinline__ void mma8(float* c, const unsigned* a, const unsigned* b) {
    asm volatile(
        "mma.sync.aligned.m16n8k8.row.col.f32.tf32.tf32.f32 "
        "{%0,%1,%2,%3},{%4,%5,%6,%7},{%8,%9},{%0,%1,%2,%3};"
        : "+f"(c[0]), "+f"(c[1]), "+f"(c[2]), "+f"(c[3])
        : "r"(a[0]), "r"(a[1]), "r"(a[2]), "r"(a[3]), "r"(b[0]), "r"(b[1]));
}

// ---------------- K0: biases, mask factors, zero accumulators ----------------
__global__ void k0_setup(const float* __restrict__ C, const float* __restrict__ Q,
                         const float* __restrict__ cmask, const float* __restrict__ qmask,
                         const float* __restrict__ w) {
    int idx = blockIdx.x * 256 + threadIdx.x;
    if (idx < B * LC) {
        int b = idx >> 10;
        int i = idx & (LC - 1);
        const float* cp = C + (size_t)b * D * LC + i;
        float s = 0.f;
#pragma unroll 4
        for (int dd = 0; dd < D; ++dd) s = fmaf(cp[(size_t)dd * LC], w[dd], s);
        g_cw1[idx] = s;
        g_fc[idx] = __expf((1.0f - cmask[idx]) * NEG_INF);
        g_rowsum[idx] = 0.f;
    } else {
        int t = idx - B * LC;
        if (t < B * LQ) {
            int b = t >> 8;
            int j = t & (LQ - 1);
            const float* qp = Q + (size_t)b * D * LQ + j;
            float s = 0.f;
#pragma unroll 4
            for (int dd = 0; dd < D; ++dd) s = fmaf(qp[(size_t)dd * LQ], w[D + dd], s);
            g_qw2[t] = s;
            g_fq[t] = __expf((1.0f - qmask[t]) * NEG_INF);
            g_colsum[t] = 0.f;
        }
    }
}

// ---------------- K1: E = exp(S) + row/col exp-sums (tf32 MMA) ---------------
// grid (LQ/128, LC/128, B), 256 thr.  M=i(128) N=j(128) K=d(128)
__global__ __launch_bounds__(256, 2) void k1_score(const float* __restrict__ C,
                                                   const float* __restrict__ Q,
                                                   const float* __restrict__ w) {
    int b = blockIdx.z, i0 = blockIdx.y * 128, j0 = blockIdx.x * 128;

    __shared__ __align__(16) unsigned SMB[2 * 32 * SA];   // As|Bs; reused as tr[64][SA]
    unsigned (*As)[SA] = (unsigned(*)[SA])SMB;
    unsigned (*Bs)[SA] = (unsigned(*)[SA])(SMB + 32 * SA);
    float* tr = (float*)SMB;
    __shared__ float scw[128], sfcs[128], sqw[128], sfqs[128], srow[128], scol[128];

    int tid = threadIdx.x;
    int wid = tid >> 5, lane = tid & 31, g = lane >> 2, t = lane & 3;
    int wm = wid & 3, wn = wid >> 2;     // warp tile: 32(m) x 64(n)

    float acc[2][8][4];
#pragma unroll
    for (int mt = 0; mt < 2; ++mt)
#pragma unroll
        for (int nt = 0; nt < 8; ++nt)
#pragma unroll
            for (int c = 0; c < 4; ++c) acc[mt][nt][c] = 0.f;

    const float* Cb = C + (size_t)b * D * LC;
    const float* Qb = Q + (size_t)b * D * LQ;

    int qm = tid & 31, kr = tid >> 5;    // loader: m-quad, k-row

    uint4 pa[4], pb[4];
#pragma unroll
    for (int p = 0; p < 4; ++p) {        // prefetch chunk 0
        int k = kr + 8 * p;
        float w3 = w[2 * D + k];
        float4 v = *(const float4*)(Cb + (size_t)k * LC + i0 + 4 * qm);
        v.x *= w3; v.y *= w3; v.z *= w3; v.w *= w3;
        pa[p] = f2t4(v);
        pb[p] = f2t4(*(const float4*)(Qb + (size_t)k * LQ + j0 + 4 * qm));
    }

    for (int kc = 0; kc < D; kc += 32) {
        __syncthreads();
#pragma unroll
        for (int p = 0; p < 4; ++p) {
            *(uint4*)&As[kr + 8 * p][4 * qm] = pa[p];
            *(uint4*)&Bs[kr + 8 * p][4 * qm] = pb[p];
        }
        __syncthreads();
        if (kc + 32 < D) {
#pragma unroll
            for (int p = 0; p < 4; ++p) {
                int k = kc + 32 + kr + 8 * p;
                float w3 = w[2 * D + k];
                float4 v = *(const float4*)(Cb + (size_t)k * LC + i0 + 4 * qm);
                v.x *= w3; v.y *= w3; v.z *= w3; v.w *= w3;
                pa[p] = f2t4(v);
                pb[p] = f2t4(*(const float4*)(Qb + (size_t)k * LQ + j0 + 4 * qm));
            }
        }
#pragma unroll
        for (int k8 = 0; k8 < 4; ++k8) {
            int kk = 8 * k8;
            unsigned a[2][4];
#pragma unroll
            for (int mt = 0; mt < 2; ++mt) {
                int R = wm * 32 + mt * 16 + g;
                a[mt][0] = As[kk + t][R];
                a[mt][1] = As[kk + t][R + 8];
                a[mt][2] = As[kk + t + 4][R];
                a[mt][3] = As[kk + t + 4][R + 8];
            }
#pragma unroll
            for (int nt = 0; nt < 8; ++nt) {
                int NN = wn * 64 + nt * 8 + g;
                unsigned bb[2] = { Bs[kk + t][NN], Bs[kk + t + 4][NN] };
#pragma unroll
                for (int mt = 0; mt < 2; ++mt) mma8(acc[mt][nt], a[mt], bb);
            }
        }
    }

    // ---- epilogue: exp into acc, row/col partial sums ----
    __syncthreads();
    if (tid < 128) {
        scw[tid]  = g_cw1[b * LC + i0 + tid];
        sfcs[tid] = g_fc[b * LC + i0 + tid];
        srow[tid] = 0.f;
    } else {
        int j = tid - 128;
        sqw[j]  = g_qw2[b * LQ + j0 + j];
        sfqs[j] = g_fq[b * LQ + j0 + j];
        scol[j] = 0.f;
    }
    __syncthreads();

    float rowp[4] = {0.f, 0.f, 0.f, 0.f};
    float colp[16];
#pragma unroll
    for (int c = 0; c < 16; ++c) colp[c] = 0.f;

#pragma unroll
    for (int mt = 0; mt < 2; ++mt)
#pragma unroll
        for (int half = 0; half < 2; ++half) {
            int rl = wm * 32 + mt * 16 + g + 8 * half;
            float cwv = scw[rl], fcv = sfcs[rl];
#pragma unroll
            for (int nt = 0; nt < 8; ++nt) {
                int cl = wn * 64 + nt * 8 + 2 * t;
                float e0 = __expf(acc[mt][nt][half * 2 + 0] + cwv + sqw[cl]);
                float e1 = __expf(acc[mt][nt][half * 2 + 1] + cwv + sqw[cl + 1]);
                acc[mt][nt][half * 2 + 0] = e0;
                acc[mt][nt][half * 2 + 1] = e1;
                rowp[mt * 2 + half] += e0 * sfqs[cl] + e1 * sfqs[cl + 1];
                colp[nt * 2 + 0] += e0 * fcv;
                colp[nt * 2 + 1] += e1 * fcv;
            }
        }

#pragma unroll
    for (int r = 0; r < 4; ++r) {
        rowp[r] += __shfl_xor_sync(0xffffffffu, rowp[r], 1);
        rowp[r] += __shfl_xor_sync(0xffffffffu, rowp[r], 2);
    }
    if (t == 0) {
#pragma unroll
        for (int mt = 0; mt < 2; ++mt)
#pragma unroll
            for (int half = 0; half < 2; ++half)
                atomicAdd(&srow[wm * 32 + mt * 16 + g + 8 * half], rowp[mt * 2 + half]);
    }
#pragma unroll
    for (int c = 0; c < 16; ++c) {
        colp[c] += __shfl_xor_sync(0xffffffffu, colp[c], 4);
        colp[c] += __shfl_xor_sync(0xffffffffu, colp[c], 8);
        colp[c] += __shfl_xor_sync(0xffffffffu, colp[c], 16);
    }
    if (g == 0) {
#pragma unroll
        for (int nt = 0; nt < 8; ++nt)
#pragma unroll
            for (int par = 0; par < 2; ++par)
                atomicAdd(&scol[wn * 64 + nt * 8 + 2 * t + par], colp[nt * 2 + par]);
    }
    __syncthreads();
    if (tid < 128) atomicAdd(&g_rowsum[b * LC + i0 + tid], srow[tid]);
    else           atomicAdd(&g_colsum[b * LQ + j0 + tid - 128], scol[tid - 128]);

    // ---- coalesced E store via smem transpose (2 chunks of 64 rows) ----
    int r2 = tid >> 4, c16 = tid & 15;
#pragma unroll
    for (int ch = 0; ch < 2; ++ch) {
        __syncthreads();
        if ((wm >> 1) == ch) {
#pragma unroll
            for (int mt = 0; mt < 2; ++mt)
#pragma unroll
                for (int half = 0; half < 2; ++half) {
                    int rowl = (wm & 1) * 32 + mt * 16 + g + 8 * half;
#pragma unroll
                    for (int nt = 0; nt < 8; ++nt) {
                        int col = wn * 64 + nt * 8 + 2 * t;
                        tr[rowl * SA + col]     = acc[mt][nt][half * 2 + 0];
                        tr[rowl * SA + col + 1] = acc[mt][nt][half * 2 + 1];
                    }
                }
        }
        __syncthreads();
        float* dst = g_E + ((size_t)b * LC + i0 + ch * 64) * LQ + j0;
#pragma unroll
        for (int rr = 0; rr < 4; ++rr)
#pragma unroll
            for (int seg = 0; seg < 2; ++seg) {
                int row = r2 + 16 * rr;
                *(float4*)(dst + (size_t)row * LQ + seg * 64 + 4 * c16) =
                    *(float4*)&tr[row * SA + seg * 64 + 4 * c16];
            }
    }
}

// ---------------- K4: M[j][dd] = (sum_i E[i][j]*fc[i]*C[dd][i]) / colsum[j] --
// grid (LQ/128, B), 256 thr.  M=j(128) N=dd(128) K=i(1024)
__global__ __launch_bounds__(256, 2) void k4_m(const float* __restrict__ C) {
    int b = blockIdx.y, j0 = blockIdx.x * 128;

    __shared__ __align__(16) unsigned SMB[2 * 32 * SA];
    unsigned (*As)[SA] = (unsigned(*)[SA])SMB;
    unsigned (*Bs)[SA] = (unsigned(*)[SA])(SMB + 32 * SA);
    float* tr = (float*)SMB;

    int tid = threadIdx.x;
    int wid = tid >> 5, lane = tid & 31, g = lane >> 2, t = lane & 3;
    int wm = wid & 3, wn = wid >> 2;

    float acc[2][8][4];
#pragma unroll
    for (int mt = 0; mt < 2; ++mt)
#pragma unroll
        for (int nt = 0; nt < 8; ++nt)
#pragma unroll
            for (int c = 0; c < 4; ++c) acc[mt][nt][c] = 0.f;

    const float* Cb = C + (size_t)b * D * LC;
    const float* Eb = g_E + (size_t)b * LC * LQ;

    int qm = tid & 31, kr = tid >> 5;     // A loader
    int dd = tid & 127, kq = tid >> 7;    // B loader (transpose)

    uint4 va[4], vb[4];
#pragma unroll
    for (int p = 0; p < 4; ++p) {
        int i = kr + 8 * p;
        float f = g_fc[b * LC + i];
        float4 v = *(const float4*)(Eb + (size_t)i * LQ + j0 + 4 * qm);
        v.x *= f; v.y *= f; v.z *= f; v.w *= f;
        va[p] = f2t4(v);
        vb[p] = f2t4(*(const float4*)(Cb + (size_t)dd * LC + 4 * (kq + 2 * p)));
    }

    for (int kc = 0; kc < LC; kc += 32) {
        __syncthreads();
#pragma unroll
        for (int p = 0; p < 4; ++p) {
            *(uint4*)&As[kr + 8 * p][4 * qm] = va[p];
            int kb = 4 * (kq + 2 * p);
            Bs[kb + 0][dd] = vb[p].x;
            Bs[kb + 1][dd] = vb[p].y;
            Bs[kb + 2][dd] = vb[p].z;
            Bs[kb + 3][dd] = vb[p].w;
        }
        __syncthreads();
        if (kc + 32 < LC) {
#pragma unroll
            for (int p = 0; p < 4; ++p) {
                int i = kc + 32 + kr + 8 * p;
                float f = g_fc[b * LC + i];
                float4 v = *(const float4*)(Eb + (size_t)i * LQ + j0 + 4 * qm);
                v.x *= f; v.y *= f; v.z *= f; v.w *= f;
                va[p] = f2t4(v);
                vb[p] = f2t4(*(const float4*)(Cb + (size_t)dd * LC + kc + 32 + 4 * (kq + 2 * p)));
            }
        }
#pragma unroll
        for (int k8 = 0; k8 < 4; ++k8) {
            int kk = 8 * k8;
            unsigned a[2][4];
#pragma unroll
            for (int mt = 0; mt < 2; ++mt) {
                int R = wm * 32 + mt * 16 + g;
                a[mt][0] = As[kk + t][R];
                a[mt][1] = As[kk + t][R + 8];
                a[mt][2] = As[kk + t + 4][R];
                a[mt][3] = As[kk + t + 4][R + 8];
            }
#pragma unroll
            for (int nt = 0; nt < 8; ++nt) {
                int NN = wn * 64 + nt * 8 + g;
                unsigned bb[2] = { Bs[kk + t][NN], Bs[kk + t + 4][NN] };
#pragma unroll
                for (int mt = 0; mt < 2; ++mt) mma8(acc[mt][nt], a[mt], bb);
            }
        }
    }

    // ---- coalesced M store via smem transpose (2 chunks of 64 j-rows) ----
    int r2 = tid >> 4, c16 = tid & 15;
#pragma unroll
    for (int ch = 0; ch < 2; ++ch) {
        __syncthreads();
        if ((wm >> 1) == ch) {
#pragma unroll
            for (int mt = 0; mt < 2; ++mt)
#pragma unroll
                for (int half = 0; half < 2; ++half) {
                    int rowl = (wm & 1) * 32 + mt * 16 + g + 8 * half;
                    float ci = 1.0f / g_colsum[b * LQ + j0 + ch * 64 + rowl];
#pragma unroll
                    for (int nt = 0; nt < 8; ++nt) {
                        int col = wn * 64 + nt * 8 + 2 * t;
                        tr[rowl * SA + col]     = acc[mt][nt][half * 2 + 0] * ci;
                        tr[rowl * SA + col + 1] = acc[mt][nt][half * 2 + 1] * ci;
                    }
                }
        }
        __syncthreads();
        float* dst = g_M + ((size_t)b * LQ + j0 + ch * 64) * D;
#pragma unroll
        for (int rr = 0; rr < 4; ++rr)
#pragma unroll
            for (int seg = 0; seg < 2; ++seg) {
                int row = r2 + 16 * rr;
                *(float4*)(dst + (size_t)row * D + seg * 64 + 4 * c16) =
                    *(float4*)&tr[row * SA + seg * 64 + 4 * c16];
            }
    }
}

// ---------------- K5: A & Bmat (dual GEMM) + 4 output channels ----------------
// grid (D/64, LC/128, B), 256 thr.  M=i(128) N=dd(64) K=j(256)
__global__ __launch_bounds__(256, 2) void k5_out(const float* __restrict__ C,
                                                 const float* __restrict__ Q,
                                                 float* __restrict__ out) {
    int b = blockIdx.z, i0 = blockIdx.y * 128, dd0 = blockIdx.x * 64;

    __shared__ __align__(16) unsigned SMB[32 * SA + 2 * 32 * SB];  // As|Bq|Bm; tr[64][SA]
    unsigned (*As)[SA] = (unsigned(*)[SA])SMB;
    unsigned (*Bq)[SB] = (unsigned(*)[SB])(SMB + 32 * SA);
    unsigned (*Bm)[SB] = (unsigned(*)[SB])(SMB + 32 * SA + 32 * SB);
    float* tr = (float*)SMB;
    __shared__ float sfq[LQ];

    int tid = threadIdx.x;
    int wid = tid >> 5, lane = tid & 31, g = lane >> 2, t = lane & 3;
    int wm = wid & 3, wn = wid >> 2;     // warp tile: 32(m) x 32(n)

    sfq[tid] = g_fq[b * LQ + tid];

    float accA[2][4][4], accB[2][4][4];
#pragma unroll
    for (int mt = 0; mt < 2; ++mt)
#pragma unroll
        for (int nt = 0; nt < 4; ++nt)
#pragma unroll
            for (int c = 0; c < 4; ++c) { accA[mt][nt][c] = 0.f; accB[mt][nt][c] = 0.f; }

    const float* Cb = C + (size_t)b * D * LC;
    const float* Qb = Q + (size_t)b * D * LQ;
    const float* Eb = g_E + (size_t)b * LC * LQ;
    const float* Mb = g_M + (size_t)b * LQ * D;

    int ia = tid & 127, kqa = tid >> 7;        // A loader (transpose)
    int dq = tid & 63,  kq2 = (tid >> 6) & 3;  // Bq loader (transpose)
    int qn = tid & 15,  krm = tid >> 4;        // Bm loader (direct)

    float4 ea[4];
    uint4 qa[2], ma[2];
#pragma unroll
    for (int p = 0; p < 4; ++p)
        ea[p] = *(const float4*)(Eb + (size_t)(i0 + ia) * LQ + 4 * (kqa + 2 * p));
#pragma unroll
    for (int p = 0; p < 2; ++p) {
        qa[p] = f2t4(*(const float4*)(Qb + (size_t)(dd0 + dq) * LQ + 4 * (kq2 + 4 * p)));
        ma[p] = f2t4(*(const float4*)(Mb + (size_t)(krm + 16 * p) * D + dd0 + 4 * qn));
    }

    for (int kc = 0; kc < LQ; kc += 32) {
        __syncthreads();
#pragma unroll
        for (int p = 0; p < 4; ++p) {
            int ka = 4 * (kqa + 2 * p);
            As[ka + 0][ia] = f2t(ea[p].x * sfq[kc + ka + 0]);
            As[ka + 1][ia] = f2t(ea[p].y * sfq[kc + ka + 1]);
            As[ka + 2][ia] = f2t(ea[p].z * sfq[kc + ka + 2]);
            As[ka + 3][ia] = f2t(ea[p].w * sfq[kc + ka + 3]);
        }
#pragma unroll
        for (int p = 0; p < 2; ++p) {
            int kb = 4 * (kq2 + 4 * p);
            Bq[kb + 0][dq] = qa[p].x;
            Bq[kb + 1][dq] = qa[p].y;
            Bq[kb + 2][dq] = qa[p].z;
            Bq[kb + 3][dq] = qa[p].w;
            *(uint4*)&Bm[krm + 16 * p][4 * qn] = ma[p];
        }
        __syncthreads();
        if (kc + 32 < LQ) {
#pragma unroll
            for (int p = 0; p < 4; ++p)
                ea[p] = *(const float4*)(Eb + (size_t)(i0 + ia) * LQ + kc + 32 + 4 * (kqa + 2 * p));
#pragma unroll
            for (int p = 0; p < 2; ++p) {
                qa[p] = f2t4(*(const float4*)(Qb + (size_t)(dd0 + dq) * LQ + kc + 32 + 4 * (kq2 + 4 * p)));
                ma[p] = f2t4(*(const float4*)(Mb + (size_t)(kc + 32 + krm + 16 * p) * D + dd0 + 4 * qn));
            }
        }
#pragma unroll
        for (int k8 = 0; k8 < 4; ++k8) {
            int kk = 8 * k8;
            unsigned a[2][4];
#pragma unroll
            for (int mt = 0; mt < 2; ++mt) {
                int R = wm * 32 + mt * 16 + g;
                a[mt][0] = As[kk + t][R];
                a[mt][1] = As[kk + t][R + 8];
                a[mt][2] = As[kk + t + 4][R];
                a[mt][3] = As[kk + t + 4][R + 8];
            }
#pragma unroll
            for (int nt = 0; nt < 4; ++nt) {
                int NN = wn * 32 + nt * 8 + g;
                unsigned bq[2] = { Bq[kk + t][NN], Bq[kk + t + 4][NN] };
                unsigned bm[2] = { Bm[kk + t][NN], Bm[kk + t + 4][NN] };
#pragma unroll
                for (int mt = 0; mt < 2; ++mt) {
                    mma8(accA[mt][nt], a[mt], bq);
                    mma8(accB[mt][nt], a[mt], bm);
                }
            }
        }
    }

    // ---- epilogue: rowsum scale, transpose in smem, coalesced stores ----
    float rinv[2][2];
#pragma unroll
    for (int mt = 0; mt < 2; ++mt)
#pragma unroll
        for (int half = 0; half < 2; ++half)
            rinv[mt][half] = 1.0f / g_rowsum[b * LC + i0 + wm * 32 + mt * 16 + g + 8 * half];

    int r2 = tid >> 4, c16 = tid & 15;
    size_t ob = (size_t)b * 4 * D * LC;
    const float* Csrc = Cb + (size_t)dd0 * LC + i0;
    float* o0 = out + ob + (size_t)dd0 * LC + i0;

    // phase A: channels 0 (Ct), 1 (A), 2 (Ct*A)
    __syncthreads();
#pragma unroll
    for (int mt = 0; mt < 2; ++mt)
#pragma unroll
        for (int half = 0; half < 2; ++half) {
            int iil = wm * 32 + mt * 16 + g + 8 * half;
#pragma unroll
            for (int nt = 0; nt < 4; ++nt) {
                int ddl = wn * 32 + nt * 8 + 2 * t;
                tr[ddl * SA + iil]       = accA[mt][nt][half * 2 + 0] * rinv[mt][half];
                tr[(ddl + 1) * SA + iil] = accA[mt][nt][half * 2 + 1] * rinv[mt][half];
            }
        }
    __syncthreads();
#pragma unroll
    for (int rr = 0; rr < 4; ++rr)
#pragma unroll
        for (int seg = 0; seg < 2; ++seg) {
            int row = r2 + 16 * rr;
            int off = seg * 64 + 4 * c16;
            float4 a4 = *(float4*)&tr[row * SA + off];
            float4 c4 = *(const float4*)(Csrc + (size_t)row * LC + off);
            size_t go = (size_t)row * LC + off;
            *(float4*)(o0 + go) = c4;
            *(float4*)(o0 + (size_t)D * LC + go) = a4;
            *(float4*)(o0 + (size_t)2 * D * LC + go) =
                make_float4(c4.x * a4.x, c4.y * a4.y, c4.z * a4.z, c4.w * a4.w);
        }

    // phase B: channel 3 (Ct*Bmat)
    __syncthreads();
#pragma unroll
    for (int mt = 0; mt < 2; ++mt)
#pragma unroll
        for (int half = 0; half < 2; ++half) {
            int iil = wm * 32 + mt * 16 + g + 8 * half;
#pragma unroll
            for (int nt = 0; nt < 4; ++nt) {
                int ddl = wn * 32 + nt * 8 + 2 * t;
                tr[ddl * SA + iil]       = accB[mt][nt][half * 2 + 0] * rinv[mt][half];
                tr[(ddl + 1) * SA + iil] = accB[mt][nt][half * 2 + 1] * rinv[mt][half];
            }
        }
    __syncthreads();
#pragma unroll
    for (int rr = 0; rr < 4; ++rr)
#pragma unroll
        for (int seg = 0; seg < 2; ++seg) {
            int row = r2 + 16 * rr;
            int off = seg * 64 + 4 * c16;
            float4 b4 = *(float4*)&tr[row * SA + off];
            float4 c4 = *(const float4*)(Csrc + (size_t)row * LC + off);
            *(float4*)(o0 + (size_t)3 * D * LC + (size_t)row * LC + off) =
                make_float4(c4.x * b4.x, c4.y * b4.y, c4.z * b4.z, c4.w * b4.w);
        }
}

// ---------------- launch ------------------------------------------------------
extern "C" void kernel_launch(void* const* d_in, const int* in_sizes, int n_in,
                              void* d_out, int out_size) {
    const float* C = (const float*)d_in[0];
    const float* Q = (const float*)d_in[1];
    const float* cmask = (const float*)d_in[2];
    const float* qmask = (const float*)d_in[3];
    const float* w = (const float*)d_in[4];
    float* out = (float*)d_out;

    k0_setup<<<(B * LC + B * LQ) / 256, 256>>>(C, Q, cmask, qmask, w);

    dim3 g1(LQ / 128, LC / 128, B);
    k1_score<<<g1, 256>>>(C, Q, w);

    dim3 g4(LQ / 128, B);
    k4_m<<<g4, 256>>>(C);

    dim3 g5(D / 64, LC / 128, B);
    k5_out<<<g5, 256>>>(C, Q, out);
}